// round 2
// baseline (speedup 1.0000x reference)
#include <cuda_runtime.h>
#include <math.h>

#define BB   2
#define SS   2048
#define HIDD 1024
#define NHH  16
#define HDD  64
#define MM   (BB * SS)   // 4096 rows

// Scratch (no runtime allocation allowed): Q, K, V projections + attention ctx
__device__ float g_q[(size_t)MM * HIDD];
__device__ float g_k[(size_t)MM * HIDD];
__device__ float g_v[(size_t)MM * HIDD];
__device__ float g_c[(size_t)MM * HIDD];

// ---------------------------------------------------------------------------
// C[M,N] = A[M,K] @ W[K,N] + bias[N]
// 64x64 block tile, 256 threads, 4x4 per-thread micro-tile, K-tile = 16.
// A tile stored transposed in smem so inner-loop reads are row-broadcasts.
// ---------------------------------------------------------------------------
__global__ __launch_bounds__(256) void gemm_bias_kernel(
    const float* __restrict__ A, const float* __restrict__ W,
    const float* __restrict__ bias, float* __restrict__ C,
    int M, int N, int K)
{
    __shared__ float As[16][64];   // [kk][m]
    __shared__ float Ws[16][64];   // [kk][n]

    const int tid  = threadIdx.x;
    const int tx   = tid & 15;
    const int ty   = tid >> 4;
    const int row0 = blockIdx.y * 64;
    const int col0 = blockIdx.x * 64;

    const int a_m  = tid >> 2;         // 0..63
    const int a_k4 = (tid & 3) << 2;   // 0,4,8,12
    const int w_k  = tid >> 4;         // 0..15
    const int w_n4 = (tid & 15) << 2;  // 0..60

    float acc[4][4] = {};

    for (int k0 = 0; k0 < K; k0 += 16) {
        float4 a4 = *reinterpret_cast<const float4*>(
            &A[(size_t)(row0 + a_m) * K + k0 + a_k4]);
        As[a_k4 + 0][a_m] = a4.x;
        As[a_k4 + 1][a_m] = a4.y;
        As[a_k4 + 2][a_m] = a4.z;
        As[a_k4 + 3][a_m] = a4.w;

        float4 w4 = *reinterpret_cast<const float4*>(
            &W[(size_t)(k0 + w_k) * N + col0 + w_n4]);
        Ws[w_k][w_n4 + 0] = w4.x;
        Ws[w_k][w_n4 + 1] = w4.y;
        Ws[w_k][w_n4 + 2] = w4.z;
        Ws[w_k][w_n4 + 3] = w4.w;

        __syncthreads();

        #pragma unroll
        for (int kk = 0; kk < 16; kk++) {
            float af[4], wf[4];
            #pragma unroll
            for (int i = 0; i < 4; i++) af[i] = As[kk][ty * 4 + i];
            #pragma unroll
            for (int j = 0; j < 4; j++) wf[j] = Ws[kk][tx * 4 + j];
            #pragma unroll
            for (int i = 0; i < 4; i++)
                #pragma unroll
                for (int j = 0; j < 4; j++)
                    acc[i][j] = fmaf(af[i], wf[j], acc[i][j]);
        }
        __syncthreads();
    }

    const int ccol = col0 + tx * 4;
    float4 b4 = *reinterpret_cast<const float4*>(&bias[ccol]);
    #pragma unroll
    for (int i = 0; i < 4; i++) {
        float4 r4;
        r4.x = acc[i][0] + b4.x;
        r4.y = acc[i][1] + b4.y;
        r4.z = acc[i][2] + b4.z;
        r4.w = acc[i][3] + b4.w;
        *reinterpret_cast<float4*>(
            &C[(size_t)(row0 + ty * 4 + i) * N + ccol]) = r4;
    }
}

// ---------------------------------------------------------------------------
// Flash-style attention per (b, h, 64-q-row tile).
// Qst/Kst stored dim-major so score-loop smem reads are row-broadcasts.
// Kst buffer is reused for P after scores are computed. Exactly 48 KB smem.
// ---------------------------------------------------------------------------
__global__ __launch_bounds__(256) void attn_kernel(
    const float* __restrict__ Q, const float* __restrict__ K,
    const float* __restrict__ V, float* __restrict__ Octx)
{
    __shared__ float Qst[64][64];  // [dim][q-row], pre-scaled
    __shared__ float Kst[64][64];  // [dim][k-row]; reused as P[q-row][k-row]
    __shared__ float Vs[64][64];   // [k-row][dim]

    const int tid = threadIdx.x;
    const int tx  = tid & 15;
    const int ty  = tid >> 4;
    const int b   = blockIdx.y >> 4;
    const int h   = blockIdx.y & 15;
    const int qt  = blockIdx.x;

    const size_t head_off = (size_t)h * HDD;
    const size_t qbase = ((size_t)b * SS + (size_t)qt * 64) * HIDD + head_off;

    const int l_r  = tid >> 2;        // 0..63
    const int l_c0 = (tid & 3) << 2;  // 0,4,8,12 (then +16 per iter)

    // Load Q tile, transposed + scaled by 1/sqrt(HD)=0.125
    #pragma unroll
    for (int it = 0; it < 4; it++) {
        int c4 = l_c0 + it * 16;
        float4 v4 = *reinterpret_cast<const float4*>(
            &Q[qbase + (size_t)l_r * HIDD + c4]);
        Qst[c4 + 0][l_r] = v4.x * 0.125f;
        Qst[c4 + 1][l_r] = v4.y * 0.125f;
        Qst[c4 + 2][l_r] = v4.z * 0.125f;
        Qst[c4 + 3][l_r] = v4.w * 0.125f;
    }

    float m_[4], l_[4], o_[4][4];
    #pragma unroll
    for (int i = 0; i < 4; i++) {
        m_[i] = -1e30f;
        l_[i] = 0.f;
        #pragma unroll
        for (int j = 0; j < 4; j++) o_[i][j] = 0.f;
    }
    __syncthreads();

    for (int kt = 0; kt < SS / 64; kt++) {
        const size_t kbase = ((size_t)b * SS + (size_t)kt * 64) * HIDD + head_off;
        #pragma unroll
        for (int it = 0; it < 4; it++) {
            int c4 = l_c0 + it * 16;
            float4 k4 = *reinterpret_cast<const float4*>(
                &K[kbase + (size_t)l_r * HIDD + c4]);
            Kst[c4 + 0][l_r] = k4.x;
            Kst[c4 + 1][l_r] = k4.y;
            Kst[c4 + 2][l_r] = k4.z;
            Kst[c4 + 3][l_r] = k4.w;
            float4 vv = *reinterpret_cast<const float4*>(
                &V[kbase + (size_t)l_r * HIDD + c4]);
            *reinterpret_cast<float4*>(&Vs[l_r][c4]) = vv;
        }
        __syncthreads();

        // Scores: s[i][j] = sum_d Qst[d][qr] * Kst[d][kr]
        float s[4][4] = {};
        #pragma unroll 8
        for (int d = 0; d < 64; d++) {
            float qf[4], kf[4];
            #pragma unroll
            for (int i = 0; i < 4; i++) qf[i] = Qst[d][ty * 4 + i];
            #pragma unroll
            for (int j = 0; j < 4; j++) kf[j] = Kst[d][tx * 4 + j];
            #pragma unroll
            for (int i = 0; i < 4; i++)
                #pragma unroll
                for (int j = 0; j < 4; j++)
                    s[i][j] = fmaf(qf[i], kf[j], s[i][j]);
        }
        __syncthreads();  // everyone done reading Kst before P overwrites it

        // Online softmax. Row r = ty*4+i is owned by the 16 lanes sharing ty;
        // tid = ty*16+tx -> those 16 lanes are contiguous in the warp, so
        // xor-shuffles with offsets 8,4,2,1 reduce within the row group.
        #pragma unroll
        for (int i = 0; i < 4; i++) {
            float mx = s[i][0];
            #pragma unroll
            for (int j = 1; j < 4; j++) mx = fmaxf(mx, s[i][j]);
            #pragma unroll
            for (int off = 8; off > 0; off >>= 1)
                mx = fmaxf(mx, __shfl_xor_sync(0xffffffffu, mx, off));
            float mn   = fmaxf(m_[i], mx);
            float corr = __expf(m_[i] - mn);
            float rs = 0.f;
            float p[4];
            #pragma unroll
            for (int j = 0; j < 4; j++) {
                p[j] = __expf(s[i][j] - mn);
                rs += p[j];
            }
            #pragma unroll
            for (int off = 8; off > 0; off >>= 1)
                rs += __shfl_xor_sync(0xffffffffu, rs, off);
            l_[i] = l_[i] * corr + rs;
            m_[i] = mn;
            #pragma unroll
            for (int j = 0; j < 4; j++) {
                o_[i][j] *= corr;
                Kst[ty * 4 + i][tx * 4 + j] = p[j];  // Kst reused as P
            }
        }
        __syncthreads();

        // O += P @ V : o[i][j] += sum_c P[qr][c] * Vs[c][d]
        #pragma unroll 8
        for (int c = 0; c < 64; c++) {
            float pf[4], vf[4];
            #pragma unroll
            for (int i = 0; i < 4; i++) pf[i] = Kst[ty * 4 + i][c];
            #pragma unroll
            for (int j = 0; j < 4; j++) vf[j] = Vs[c][tx * 4 + j];
            #pragma unroll
            for (int i = 0; i < 4; i++)
                #pragma unroll
                for (int j = 0; j < 4; j++)
                    o_[i][j] = fmaf(pf[i], vf[j], o_[i][j]);
        }
        __syncthreads();
    }

    #pragma unroll
    for (int i = 0; i < 4; i++) {
        float inv = 1.f / l_[i];
        float4 r4;
        r4.x = o_[i][0] * inv;
        r4.y = o_[i][1] * inv;
        r4.z = o_[i][2] * inv;
        r4.w = o_[i][3] * inv;
        *reinterpret_cast<float4*>(
            &Octx[qbase + (size_t)(ty * 4 + i) * HIDD + tx * 4]) = r4;
    }
}

// ---------------------------------------------------------------------------

extern "C" void kernel_launch(void* const* d_in, const int* in_sizes, int n_in,
                              void* d_out, int out_size)
{
    const float* query = (const float*)d_in[0];
    const float* key_  = (const float*)d_in[1];
    const float* value = (const float*)d_in[2];
    const float* Wq    = (const float*)d_in[3];
    const float* bq    = (const float*)d_in[4];
    const float* Wk    = (const float*)d_in[5];
    const float* bk    = (const float*)d_in[6];
    const float* Wv    = (const float*)d_in[7];
    const float* bv    = (const float*)d_in[8];
    const float* Wo    = (const float*)d_in[9];
    const float* bo    = (const float*)d_in[10];
    float* out = (float*)d_out;

    float *q, *k, *v, *c;
    cudaGetSymbolAddress((void**)&q, g_q);
    cudaGetSymbolAddress((void**)&k, g_k);
    cudaGetSymbolAddress((void**)&v, g_v);
    cudaGetSymbolAddress((void**)&c, g_c);

    dim3 gblk(256);
    dim3 ggrd(HIDD / 64, MM / 64);   // (16, 64)

    gemm_bias_kernel<<<ggrd, gblk>>>(query, Wq, bq, q, MM, HIDD, HIDD);
    gemm_bias_kernel<<<ggrd, gblk>>>(key_,  Wk, bk, k, MM, HIDD, HIDD);
    gemm_bias_kernel<<<ggrd, gblk>>>(value, Wv, bv, v, MM, HIDD, HIDD);

    attn_kernel<<<dim3(SS / 64, BB * NHH), 256>>>(q, k, v, c);

    gemm_bias_kernel<<<ggrd, gblk>>>(c, Wo, bo, out, MM, HIDD, HIDD);
}

// round 4
// speedup vs baseline: 1.4626x; 1.4626x over previous
#include <cuda_runtime.h>
#include <cuda_bf16.h>
#include <stdint.h>
#include <math.h>

#define BB   2
#define SS   2048
#define HIDD 1024
#define NHH  16
#define HDD  64
#define MM   (BB * SS)   // 4096 rows

// ---------------------------------------------------------------------------
// Scratch (no runtime allocation allowed)
// ---------------------------------------------------------------------------
__device__ float g_q[(size_t)MM * HIDD];
__device__ float g_k[(size_t)MM * HIDD];
__device__ float g_v[(size_t)MM * HIDD];
__device__ float g_c[(size_t)MM * HIDD];
__device__ __nv_bfloat16 g_ahi[(size_t)MM * HIDD];
__device__ __nv_bfloat16 g_alo[(size_t)MM * HIDD];
__device__ __nv_bfloat16 g_wthi[(size_t)HIDD * HIDD];  // W^T hi  [n][k]
__device__ __nv_bfloat16 g_wtlo[(size_t)HIDD * HIDD];  // W^T lo  [n][k]

// ---------------------------------------------------------------------------
// PTX helpers (portable: sm_80+ instructions only)
// ---------------------------------------------------------------------------
__device__ __forceinline__ uint32_t smem_u32(const void* p) {
    uint32_t a;
    asm("{ .reg .u64 t; cvta.to.shared.u64 t, %1; cvt.u32.u64 %0, t; }"
        : "=r"(a) : "l"(p));
    return a;
}

__device__ __forceinline__ void cp16(uint32_t saddr, const void* g) {
    asm volatile("cp.async.cg.shared.global [%0], [%1], 16;"
                 :: "r"(saddr), "l"(g) : "memory");
}
__device__ __forceinline__ void cp_commit() {
    asm volatile("cp.async.commit_group;" ::: "memory");
}
__device__ __forceinline__ void cp_wait1() {
    asm volatile("cp.async.wait_group 1;" ::: "memory");
}
__device__ __forceinline__ void cp_wait0() {
    asm volatile("cp.async.wait_group 0;" ::: "memory");
}

__device__ __forceinline__ void ldm4(uint32_t* r, uint32_t addr) {
    asm volatile("ldmatrix.sync.aligned.m8n8.x4.shared.b16 {%0,%1,%2,%3}, [%4];"
                 : "=r"(r[0]), "=r"(r[1]), "=r"(r[2]), "=r"(r[3]) : "r"(addr));
}

__device__ __forceinline__ void mma_bf16(float* c, const uint32_t* a,
                                         const uint32_t* b) {
    asm volatile(
        "mma.sync.aligned.m16n8k16.row.col.f32.bf16.bf16.f32 "
        "{%0,%1,%2,%3}, {%4,%5,%6,%7}, {%8,%9}, {%0,%1,%2,%3};"
        : "+f"(c[0]), "+f"(c[1]), "+f"(c[2]), "+f"(c[3])
        : "r"(a[0]), "r"(a[1]), "r"(a[2]), "r"(a[3]), "r"(b[0]), "r"(b[1]));
}

// ---------------------------------------------------------------------------
// fp32 -> bf16 hi/lo split (elementwise, float4 vectorized)
// ---------------------------------------------------------------------------
__global__ __launch_bounds__(256) void split_kernel(
    const float* __restrict__ x, __nv_bfloat16* __restrict__ hi,
    __nv_bfloat16* __restrict__ lo, int n4)
{
    int i = blockIdx.x * 256 + threadIdx.x;
    if (i >= n4) return;
    float4 v = reinterpret_cast<const float4*>(x)[i];
    float f[4] = {v.x, v.y, v.z, v.w};
    unsigned short hs[4], ls[4];
    #pragma unroll
    for (int j = 0; j < 4; j++) {
        __nv_bfloat16 h = __float2bfloat16(f[j]);
        __nv_bfloat16 l = __float2bfloat16(f[j] - __bfloat162float(h));
        hs[j] = __bfloat16_as_ushort(h);
        ls[j] = __bfloat16_as_ushort(l);
    }
    uint2 ho, llo;
    ho.x  = (uint32_t)hs[0] | ((uint32_t)hs[1] << 16);
    ho.y  = (uint32_t)hs[2] | ((uint32_t)hs[3] << 16);
    llo.x = (uint32_t)ls[0] | ((uint32_t)ls[1] << 16);
    llo.y = (uint32_t)ls[2] | ((uint32_t)ls[3] << 16);
    reinterpret_cast<uint2*>(hi)[i] = ho;
    reinterpret_cast<uint2*>(lo)[i] = llo;
}

// ---------------------------------------------------------------------------
// W [K][N] fp32 -> W^T [N][K] bf16 hi/lo (tiled transpose)
// ---------------------------------------------------------------------------
__global__ __launch_bounds__(256) void splitT_kernel(
    const float* __restrict__ W, __nv_bfloat16* __restrict__ Th,
    __nv_bfloat16* __restrict__ Tl)
{
    __shared__ float t[32][33];
    int n0 = blockIdx.x * 32, k0 = blockIdx.y * 32;
    int tx = threadIdx.x & 31, ty = threadIdx.x >> 5;  // 32 x 8
    #pragma unroll
    for (int i = 0; i < 4; i++)
        t[ty + i * 8][tx] = W[(size_t)(k0 + ty + i * 8) * HIDD + n0 + tx];
    __syncthreads();
    #pragma unroll
    for (int i = 0; i < 4; i++) {
        float x = t[tx][ty + i * 8];
        __nv_bfloat16 h = __float2bfloat16(x);
        __nv_bfloat16 l = __float2bfloat16(x - __bfloat162float(h));
        size_t o = (size_t)(n0 + ty + i * 8) * HIDD + k0 + tx;
        Th[o] = h;
        Tl[o] = l;
    }
}

// ---------------------------------------------------------------------------
// HMMA (mma.sync bf16, 3x emulation) GEMM: C[M,N] = A @ W + bias
// W^T given as [N][K]. CTA tile 128x128, K-chunk 32, cp.async double buffer.
// smem tiles padded to 40 elems/row (80B: 5x16B chunks, odd -> ldmatrix
// conflict-free). Per stage: Ahi, Alo, Bhi, Blo = 4 x 128 x 40 bf16.
// ---------------------------------------------------------------------------
#define TPAD 40
#define TILE_E (128 * TPAD)        // elems per tile
#define TILE_B (TILE_E * 2)        // bytes per tile (10240)
#define STAGE_B (4 * TILE_B)       // 40960
#define GSMEM (2 * STAGE_B)        // 81920
#define NCHUNK (HIDD / 32)         // 32

__global__ __launch_bounds__(256, 1) void mma_gemm_kernel(
    const __nv_bfloat16* __restrict__ Ahi, const __nv_bfloat16* __restrict__ Alo,
    const __nv_bfloat16* __restrict__ Bth, const __nv_bfloat16* __restrict__ Btl,
    const float* __restrict__ bias, float* __restrict__ C)
{
    extern __shared__ __nv_bfloat16 sm[];
    const uint32_t smb = smem_u32(sm);

    const int tid  = threadIdx.x;
    const int wid  = tid >> 5, lane = tid & 31;
    const int m0   = blockIdx.y * 128, n0 = blockIdx.x * 128;
    const int wm   = (wid >> 1) * 32;   // warp m offset in tile
    const int wn   = (wid & 1) * 64;    // warp n offset in tile

    // global->smem staging indices: 2 threads per row, 16 elems each
    const int lrow = tid >> 1;
    const int lcol = (tid & 1) * 16;
    const size_t gA = (size_t)(m0 + lrow) * HIDD + lcol;
    const size_t gB = (size_t)(n0 + lrow) * HIDD + lcol;
    const uint32_t sO = smb + (uint32_t)(lrow * TPAD + lcol) * 2;

    float acc[2][8][4];
    #pragma unroll
    for (int im = 0; im < 2; im++)
        #pragma unroll
        for (int in = 0; in < 8; in++)
            #pragma unroll
            for (int j = 0; j < 4; j++) acc[im][in][j] = 0.f;

    // ldmatrix per-lane addresses (byte offsets within a tile)
    const int a_row = wm + (lane & 15);
    const int a_col = (lane >> 4) << 3;
    const int b_row = wn + (lane & 7) + ((lane & 16) ? 8 : 0);
    const int b_col = (lane & 8) ? 8 : 0;
    const uint32_t aOff = (uint32_t)(a_row * TPAD + a_col) * 2;
    const uint32_t bOff = (uint32_t)(b_row * TPAD + b_col) * 2;

    // ---- prologue: issue chunk 0 into stage 0
    {
        const int kc = 0, s = 0;
        uint32_t so = sO + s * STAGE_B;
        size_t ga = gA + kc * 32, gb = gB + kc * 32;
        cp16(so,              Ahi + ga); cp16(so + 16,              Ahi + ga + 8);
        cp16(so + TILE_B,     Alo + ga); cp16(so + TILE_B + 16,     Alo + ga + 8);
        cp16(so + 2*TILE_B,   Bth + gb); cp16(so + 2*TILE_B + 16,   Bth + gb + 8);
        cp16(so + 3*TILE_B,   Btl + gb); cp16(so + 3*TILE_B + 16,   Btl + gb + 8);
        cp_commit();
    }

    for (int kc = 0; kc < NCHUNK; kc++) {
        const int s = kc & 1;
        if (kc + 1 < NCHUNK) {
            uint32_t so = sO + (s ^ 1) * STAGE_B;
            size_t ga = gA + (kc + 1) * 32, gb = gB + (kc + 1) * 32;
            cp16(so,              Ahi + ga); cp16(so + 16,              Ahi + ga + 8);
            cp16(so + TILE_B,     Alo + ga); cp16(so + TILE_B + 16,     Alo + ga + 8);
            cp16(so + 2*TILE_B,   Bth + gb); cp16(so + 2*TILE_B + 16,   Bth + gb + 8);
            cp16(so + 3*TILE_B,   Btl + gb); cp16(so + 3*TILE_B + 16,   Btl + gb + 8);
            cp_commit();
            cp_wait1();
        } else {
            cp_wait0();
        }
        __syncthreads();

        const uint32_t st = smb + s * STAGE_B;
        #pragma unroll
        for (int ks = 0; ks < 32; ks += 16) {
            uint32_t aH[2][4], aL[2][4], bH[8][2], bL[8][2];
            #pragma unroll
            for (int im = 0; im < 2; im++) {
                ldm4(aH[im], st + aOff + (uint32_t)(im * 16 * TPAD + ks) * 2);
                ldm4(aL[im], st + TILE_B + aOff + (uint32_t)(im * 16 * TPAD + ks) * 2);
            }
            #pragma unroll
            for (int ib = 0; ib < 4; ib++) {
                uint32_t r[4];
                ldm4(r, st + 2*TILE_B + bOff + (uint32_t)(ib * 16 * TPAD + ks) * 2);
                bH[ib*2][0] = r[0]; bH[ib*2][1] = r[1];
                bH[ib*2+1][0] = r[2]; bH[ib*2+1][1] = r[3];
                ldm4(r, st + 3*TILE_B + bOff + (uint32_t)(ib * 16 * TPAD + ks) * 2);
                bL[ib*2][0] = r[0]; bL[ib*2][1] = r[1];
                bL[ib*2+1][0] = r[2]; bL[ib*2+1][1] = r[3];
            }
            #pragma unroll
            for (int im = 0; im < 2; im++)
                #pragma unroll
                for (int in = 0; in < 8; in++) {
                    mma_bf16(acc[im][in], aH[im], bH[in]);
                    mma_bf16(acc[im][in], aL[im], bH[in]);
                    mma_bf16(acc[im][in], aH[im], bL[in]);
                }
        }
        __syncthreads();
    }

    // ---- epilogue
    const int er = lane >> 2, ec = (lane & 3) * 2;
    #pragma unroll
    for (int im = 0; im < 2; im++) {
        #pragma unroll
        for (int in = 0; in < 8; in++) {
            const int n = n0 + wn + in * 8 + ec;
            const float bx = bias[n], by = bias[n + 1];
            const int mA = m0 + wm + im * 16 + er;
            float2 v0 = {acc[im][in][0] + bx, acc[im][in][1] + by};
            *reinterpret_cast<float2*>(C + (size_t)mA * HIDD + n) = v0;
            float2 v1 = {acc[im][in][2] + bx, acc[im][in][3] + by};
            *reinterpret_cast<float2*>(C + (size_t)(mA + 8) * HIDD + n) = v1;
        }
    }
}

// ---------------------------------------------------------------------------
// Flash-style SIMT attention (unchanged, proven correct)
// ---------------------------------------------------------------------------
__global__ __launch_bounds__(256) void attn_kernel(
    const float* __restrict__ Q, const float* __restrict__ K,
    const float* __restrict__ V, float* __restrict__ Octx)
{
    __shared__ float Qst[64][64];
    __shared__ float Kst[64][64];
    __shared__ float Vs[64][64];

    const int tid = threadIdx.x;
    const int tx  = tid & 15;
    const int ty  = tid >> 4;
    const int b   = blockIdx.y >> 4;
    const int h   = blockIdx.y & 15;
    const int qt  = blockIdx.x;

    const size_t head_off = (size_t)h * HDD;
    const size_t qbase = ((size_t)b * SS + (size_t)qt * 64) * HIDD + head_off;

    const int l_r  = tid >> 2;
    const int l_c0 = (tid & 3) << 2;

    #pragma unroll
    for (int it = 0; it < 4; it++) {
        int c4 = l_c0 + it * 16;
        float4 v4 = *reinterpret_cast<const float4*>(
            &Q[qbase + (size_t)l_r * HIDD + c4]);
        Qst[c4 + 0][l_r] = v4.x * 0.125f;
        Qst[c4 + 1][l_r] = v4.y * 0.125f;
        Qst[c4 + 2][l_r] = v4.z * 0.125f;
        Qst[c4 + 3][l_r] = v4.w * 0.125f;
    }

    float m_[4], l_[4], o_[4][4];
    #pragma unroll
    for (int i = 0; i < 4; i++) {
        m_[i] = -1e30f;
        l_[i] = 0.f;
        #pragma unroll
        for (int j = 0; j < 4; j++) o_[i][j] = 0.f;
    }
    __syncthreads();

    for (int kt = 0; kt < SS / 64; kt++) {
        const size_t kbase = ((size_t)b * SS + (size_t)kt * 64) * HIDD + head_off;
        #pragma unroll
        for (int it = 0; it < 4; it++) {
            int c4 = l_c0 + it * 16;
            float4 k4 = *reinterpret_cast<const float4*>(
                &K[kbase + (size_t)l_r * HIDD + c4]);
            Kst[c4 + 0][l_r] = k4.x;
            Kst[c4 + 1][l_r] = k4.y;
            Kst[c4 + 2][l_r] = k4.z;
            Kst[c4 + 3][l_r] = k4.w;
            float4 vv = *reinterpret_cast<const float4*>(
                &V[kbase + (size_t)l_r * HIDD + c4]);
            *reinterpret_cast<float4*>(&Vs[l_r][c4]) = vv;
        }
        __syncthreads();

        float s[4][4] = {};
        #pragma unroll 8
        for (int d = 0; d < 64; d++) {
            float qf[4], kf[4];
            #pragma unroll
            for (int i = 0; i < 4; i++) qf[i] = Qst[d][ty * 4 + i];
            #pragma unroll
            for (int j = 0; j < 4; j++) kf[j] = Kst[d][tx * 4 + j];
            #pragma unroll
            for (int i = 0; i < 4; i++)
                #pragma unroll
                for (int j = 0; j < 4; j++)
                    s[i][j] = fmaf(qf[i], kf[j], s[i][j]);
        }
        __syncthreads();

        #pragma unroll
        for (int i = 0; i < 4; i++) {
            float mx = s[i][0];
            #pragma unroll
            for (int j = 1; j < 4; j++) mx = fmaxf(mx, s[i][j]);
            #pragma unroll
            for (int off = 8; off > 0; off >>= 1)
                mx = fmaxf(mx, __shfl_xor_sync(0xffffffffu, mx, off));
            float mn   = fmaxf(m_[i], mx);
            float corr = __expf(m_[i] - mn);
            float rs = 0.f;
            float p[4];
            #pragma unroll
            for (int j = 0; j < 4; j++) {
                p[j] = __expf(s[i][j] - mn);
                rs += p[j];
            }
            #pragma unroll
            for (int off = 8; off > 0; off >>= 1)
                rs += __shfl_xor_sync(0xffffffffu, rs, off);
            l_[i] = l_[i] * corr + rs;
            m_[i] = mn;
            #pragma unroll
            for (int j = 0; j < 4; j++) {
                o_[i][j] *= corr;
                Kst[ty * 4 + i][tx * 4 + j] = p[j];
            }
        }
        __syncthreads();

        #pragma unroll 8
        for (int c = 0; c < 64; c++) {
            float pf[4], vf[4];
            #pragma unroll
            for (int i = 0; i < 4; i++) pf[i] = Kst[ty * 4 + i][c];
            #pragma unroll
            for (int j = 0; j < 4; j++) vf[j] = Vs[c][tx * 4 + j];
            #pragma unroll
            for (int i = 0; i < 4; i++)
                #pragma unroll
                for (int j = 0; j < 4; j++)
                    o_[i][j] = fmaf(pf[i], vf[j], o_[i][j]);
        }
        __syncthreads();
    }

    #pragma unroll
    for (int i = 0; i < 4; i++) {
        float inv = 1.f / l_[i];
        float4 r4;
        r4.x = o_[i][0] * inv;
        r4.y = o_[i][1] * inv;
        r4.z = o_[i][2] * inv;
        r4.w = o_[i][3] * inv;
        *reinterpret_cast<float4*>(
            &Octx[qbase + (size_t)(ty * 4 + i) * HIDD + tx * 4]) = r4;
    }
}

// ---------------------------------------------------------------------------

extern "C" void kernel_launch(void* const* d_in, const int* in_sizes, int n_in,
                              void* d_out, int out_size)
{
    const float* query = (const float*)d_in[0];
    const float* key_  = (const float*)d_in[1];
    const float* value = (const float*)d_in[2];
    const float* Wq    = (const float*)d_in[3];
    const float* bq    = (const float*)d_in[4];
    const float* Wk    = (const float*)d_in[5];
    const float* bk    = (const float*)d_in[6];
    const float* Wv    = (const float*)d_in[7];
    const float* bv    = (const float*)d_in[8];
    const float* Wo    = (const float*)d_in[9];
    const float* bo    = (const float*)d_in[10];
    float* out = (float*)d_out;

    float *q, *k, *v, *c;
    __nv_bfloat16 *ahi, *alo, *wthi, *wtlo;
    cudaGetSymbolAddress((void**)&q, g_q);
    cudaGetSymbolAddress((void**)&k, g_k);
    cudaGetSymbolAddress((void**)&v, g_v);
    cudaGetSymbolAddress((void**)&c, g_c);
    cudaGetSymbolAddress((void**)&ahi, g_ahi);
    cudaGetSymbolAddress((void**)&alo, g_alo);
    cudaGetSymbolAddress((void**)&wthi, g_wthi);
    cudaGetSymbolAddress((void**)&wtlo, g_wtlo);

    cudaFuncSetAttribute(mma_gemm_kernel,
                         cudaFuncAttributeMaxDynamicSharedMemorySize, GSMEM);

    const int n4_act = MM * HIDD / 4;
    dim3 tgrid(HIDD / 128, MM / 128);   // (8, 32)
    dim3 trgrid(32, 32);

    // Q projection
    split_kernel<<<n4_act / 256, 256>>>(query, ahi, alo, n4_act);
    splitT_kernel<<<trgrid, 256>>>(Wq, wthi, wtlo);
    mma_gemm_kernel<<<tgrid, 256, GSMEM>>>(ahi, alo, wthi, wtlo, bq, q);
    // K projection
    split_kernel<<<n4_act / 256, 256>>>(key_, ahi, alo, n4_act);
    splitT_kernel<<<trgrid, 256>>>(Wk, wthi, wtlo);
    mma_gemm_kernel<<<tgrid, 256, GSMEM>>>(ahi, alo, wthi, wtlo, bk, k);
    // V projection
    split_kernel<<<n4_act / 256, 256>>>(value, ahi, alo, n4_act);
    splitT_kernel<<<trgrid, 256>>>(Wv, wthi, wtlo);
    mma_gemm_kernel<<<tgrid, 256, GSMEM>>>(ahi, alo, wthi, wtlo, bv, v);

    // Attention (SIMT, fp32)
    attn_kernel<<<dim3(SS / 64, BB * NHH), 256>>>(q, k, v, c);

    // Output projection
    split_kernel<<<n4_act / 256, 256>>>(c, ahi, alo, n4_act);
    splitT_kernel<<<trgrid, 256>>>(Wo, wthi, wtlo);
    mma_gemm_kernel<<<tgrid, 256, GSMEM>>>(ahi, alo, wthi, wtlo, bo, out);
}

// round 5
// speedup vs baseline: 2.1991x; 1.5036x over previous
#include <cuda_runtime.h>
#include <cuda_bf16.h>
#include <stdint.h>
#include <math.h>

#define BB   2
#define SS   2048
#define HIDD 1024
#define NHH  16
#define HDD  64
#define MM   (BB * SS)   // 4096 rows

// ---------------------------------------------------------------------------
// Scratch
// ---------------------------------------------------------------------------
__device__ float g_q[(size_t)MM * HIDD];
__device__ float g_k[(size_t)MM * HIDD];
__device__ float g_v[(size_t)MM * HIDD];
__device__ float g_c[(size_t)MM * HIDD];
__device__ __nv_bfloat16 g_ahi[(size_t)MM * HIDD];
__device__ __nv_bfloat16 g_alo[(size_t)MM * HIDD];
__device__ __nv_bfloat16 g_wthi[(size_t)HIDD * HIDD];  // W^T hi  [n][k]
__device__ __nv_bfloat16 g_wtlo[(size_t)HIDD * HIDD];  // W^T lo  [n][k]

// ---------------------------------------------------------------------------
// PTX helpers (sm_80+ portable)
// ---------------------------------------------------------------------------
__device__ __forceinline__ uint32_t smem_u32(const void* p) {
    uint32_t a;
    asm("{ .reg .u64 t; cvta.to.shared.u64 t, %1; cvt.u32.u64 %0, t; }"
        : "=r"(a) : "l"(p));
    return a;
}
__device__ __forceinline__ void cp16(uint32_t saddr, const void* g) {
    asm volatile("cp.async.cg.shared.global [%0], [%1], 16;"
                 :: "r"(saddr), "l"(g) : "memory");
}
__device__ __forceinline__ void cp_commit() {
    asm volatile("cp.async.commit_group;" ::: "memory");
}
__device__ __forceinline__ void cp_wait1() {
    asm volatile("cp.async.wait_group 1;" ::: "memory");
}
__device__ __forceinline__ void cp_wait0() {
    asm volatile("cp.async.wait_group 0;" ::: "memory");
}
__device__ __forceinline__ void ldm4(uint32_t* r, uint32_t addr) {
    asm volatile("ldmatrix.sync.aligned.m8n8.x4.shared.b16 {%0,%1,%2,%3}, [%4];"
                 : "=r"(r[0]), "=r"(r[1]), "=r"(r[2]), "=r"(r[3]) : "r"(addr));
}
__device__ __forceinline__ void mma_bf16(float* c, const uint32_t* a,
                                         const uint32_t* b) {
    asm volatile(
        "mma.sync.aligned.m16n8k16.row.col.f32.bf16.bf16.f32 "
        "{%0,%1,%2,%3}, {%4,%5,%6,%7}, {%8,%9}, {%0,%1,%2,%3};"
        : "+f"(c[0]), "+f"(c[1]), "+f"(c[2]), "+f"(c[3])
        : "r"(a[0]), "r"(a[1]), "r"(a[2]), "r"(a[3]), "r"(b[0]), "r"(b[1]));
}
__device__ __forceinline__ uint32_t pack2bf(float a, float b) {
    return (uint32_t)__bfloat16_as_ushort(__float2bfloat16(a)) |
           ((uint32_t)__bfloat16_as_ushort(__float2bfloat16(b)) << 16);
}

// ---------------------------------------------------------------------------
// fp32 -> bf16 hi/lo split
// ---------------------------------------------------------------------------
__global__ __launch_bounds__(256) void split_kernel(
    const float* __restrict__ x, __nv_bfloat16* __restrict__ hi,
    __nv_bfloat16* __restrict__ lo, int n4)
{
    int i = blockIdx.x * 256 + threadIdx.x;
    if (i >= n4) return;
    float4 v = reinterpret_cast<const float4*>(x)[i];
    float f[4] = {v.x, v.y, v.z, v.w};
    unsigned short hs[4], ls[4];
    #pragma unroll
    for (int j = 0; j < 4; j++) {
        __nv_bfloat16 h = __float2bfloat16(f[j]);
        __nv_bfloat16 l = __float2bfloat16(f[j] - __bfloat162float(h));
        hs[j] = __bfloat16_as_ushort(h);
        ls[j] = __bfloat16_as_ushort(l);
    }
    uint2 ho, llo;
    ho.x  = (uint32_t)hs[0] | ((uint32_t)hs[1] << 16);
    ho.y  = (uint32_t)hs[2] | ((uint32_t)hs[3] << 16);
    llo.x = (uint32_t)ls[0] | ((uint32_t)ls[1] << 16);
    llo.y = (uint32_t)ls[2] | ((uint32_t)ls[3] << 16);
    reinterpret_cast<uint2*>(hi)[i] = ho;
    reinterpret_cast<uint2*>(lo)[i] = llo;
}

// ---------------------------------------------------------------------------
// W [K][N] fp32 -> W^T [N][K] bf16 hi/lo
// ---------------------------------------------------------------------------
__global__ __launch_bounds__(256) void splitT_kernel(
    const float* __restrict__ W, __nv_bfloat16* __restrict__ Th,
    __nv_bfloat16* __restrict__ Tl)
{
    __shared__ float t[32][33];
    int n0 = blockIdx.x * 32, k0 = blockIdx.y * 32;
    int tx = threadIdx.x & 31, ty = threadIdx.x >> 5;
    #pragma unroll
    for (int i = 0; i < 4; i++)
        t[ty + i * 8][tx] = W[(size_t)(k0 + ty + i * 8) * HIDD + n0 + tx];
    __syncthreads();
    #pragma unroll
    for (int i = 0; i < 4; i++) {
        float x = t[tx][ty + i * 8];
        __nv_bfloat16 h = __float2bfloat16(x);
        __nv_bfloat16 l = __float2bfloat16(x - __bfloat162float(h));
        size_t o = (size_t)(n0 + ty + i * 8) * HIDD + k0 + tx;
        Th[o] = h;
        Tl[o] = l;
    }
}

// ---------------------------------------------------------------------------
// HMMA 3x-emulated GEMM: C[M,N] = A @ W + bias (unchanged, proven)
// ---------------------------------------------------------------------------
#define TPAD 40
#define TILE_E (128 * TPAD)
#define TILE_B (TILE_E * 2)
#define STAGE_B (4 * TILE_B)
#define GSMEM (2 * STAGE_B)
#define NCHUNK (HIDD / 32)

__global__ __launch_bounds__(256, 1) void mma_gemm_kernel(
    const __nv_bfloat16* __restrict__ Ahi, const __nv_bfloat16* __restrict__ Alo,
    const __nv_bfloat16* __restrict__ Bth, const __nv_bfloat16* __restrict__ Btl,
    const float* __restrict__ bias, float* __restrict__ C)
{
    extern __shared__ __nv_bfloat16 sm[];
    const uint32_t smb = smem_u32(sm);

    const int tid  = threadIdx.x;
    const int wid  = tid >> 5, lane = tid & 31;
    const int m0   = blockIdx.y * 128, n0 = blockIdx.x * 128;
    const int wm   = (wid >> 1) * 32;
    const int wn   = (wid & 1) * 64;

    const int lrow = tid >> 1;
    const int lcol = (tid & 1) * 16;
    const size_t gA = (size_t)(m0 + lrow) * HIDD + lcol;
    const size_t gB = (size_t)(n0 + lrow) * HIDD + lcol;
    const uint32_t sO = smb + (uint32_t)(lrow * TPAD + lcol) * 2;

    float acc[2][8][4];
    #pragma unroll
    for (int im = 0; im < 2; im++)
        #pragma unroll
        for (int in = 0; in < 8; in++)
            #pragma unroll
            for (int j = 0; j < 4; j++) acc[im][in][j] = 0.f;

    const int a_row = wm + (lane & 15);
    const int a_col = (lane >> 4) << 3;
    const int b_row = wn + (lane & 7) + ((lane & 16) ? 8 : 0);
    const int b_col = (lane & 8) ? 8 : 0;
    const uint32_t aOff = (uint32_t)(a_row * TPAD + a_col) * 2;
    const uint32_t bOff = (uint32_t)(b_row * TPAD + b_col) * 2;

    {
        uint32_t so = sO;
        cp16(so,              Ahi + gA); cp16(so + 16,              Ahi + gA + 8);
        cp16(so + TILE_B,     Alo + gA); cp16(so + TILE_B + 16,     Alo + gA + 8);
        cp16(so + 2*TILE_B,   Bth + gB); cp16(so + 2*TILE_B + 16,   Bth + gB + 8);
        cp16(so + 3*TILE_B,   Btl + gB); cp16(so + 3*TILE_B + 16,   Btl + gB + 8);
        cp_commit();
    }

    for (int kc = 0; kc < NCHUNK; kc++) {
        const int s = kc & 1;
        if (kc + 1 < NCHUNK) {
            uint32_t so = sO + (s ^ 1) * STAGE_B;
            size_t ga = gA + (kc + 1) * 32, gb = gB + (kc + 1) * 32;
            cp16(so,              Ahi + ga); cp16(so + 16,              Ahi + ga + 8);
            cp16(so + TILE_B,     Alo + ga); cp16(so + TILE_B + 16,     Alo + ga + 8);
            cp16(so + 2*TILE_B,   Bth + gb); cp16(so + 2*TILE_B + 16,   Bth + gb + 8);
            cp16(so + 3*TILE_B,   Btl + gb); cp16(so + 3*TILE_B + 16,   Btl + gb + 8);
            cp_commit();
            cp_wait1();
        } else {
            cp_wait0();
        }
        __syncthreads();

        const uint32_t st = smb + s * STAGE_B;
        #pragma unroll
        for (int ks = 0; ks < 32; ks += 16) {
            uint32_t aH[2][4], aL[2][4], bH[8][2], bL[8][2];
            #pragma unroll
            for (int im = 0; im < 2; im++) {
                ldm4(aH[im], st + aOff + (uint32_t)(im * 16 * TPAD + ks) * 2);
                ldm4(aL[im], st + TILE_B + aOff + (uint32_t)(im * 16 * TPAD + ks) * 2);
            }
            #pragma unroll
            for (int ib = 0; ib < 4; ib++) {
                uint32_t r[4];
                ldm4(r, st + 2*TILE_B + bOff + (uint32_t)(ib * 16 * TPAD + ks) * 2);
                bH[ib*2][0] = r[0]; bH[ib*2][1] = r[1];
                bH[ib*2+1][0] = r[2]; bH[ib*2+1][1] = r[3];
                ldm4(r, st + 3*TILE_B + bOff + (uint32_t)(ib * 16 * TPAD + ks) * 2);
                bL[ib*2][0] = r[0]; bL[ib*2][1] = r[1];
                bL[ib*2+1][0] = r[2]; bL[ib*2+1][1] = r[3];
            }
            #pragma unroll
            for (int im = 0; im < 2; im++)
                #pragma unroll
                for (int in = 0; in < 8; in++) {
                    mma_bf16(acc[im][in], aH[im], bH[in]);
                    mma_bf16(acc[im][in], aL[im], bH[in]);
                    mma_bf16(acc[im][in], aH[im], bL[in]);
                }
        }
        __syncthreads();
    }

    const int er = lane >> 2, ec = (lane & 3) * 2;
    #pragma unroll
    for (int im = 0; im < 2; im++) {
        #pragma unroll
        for (int in = 0; in < 8; in++) {
            const int n = n0 + wn + in * 8 + ec;
            const float bx = bias[n], by = bias[n + 1];
            const int mA = m0 + wm + im * 16 + er;
            float2 v0 = {acc[im][in][0] + bx, acc[im][in][1] + by};
            *reinterpret_cast<float2*>(C + (size_t)mA * HIDD + n) = v0;
            float2 v1 = {acc[im][in][2] + bx, acc[im][in][3] + by};
            *reinterpret_cast<float2*>(C + (size_t)(mA + 8) * HIDD + n) = v1;
        }
    }
}

// ---------------------------------------------------------------------------
// HMMA flash attention, hi/lo 3x emulation everywhere.
// Block = (b, h, 128 q rows), 8 warps x 16 q rows. KV tile = 64.
// smem (bf16, rows padded to 72): Qh[128][72] Ql[128][72]
//   Kh[64][72] Kl[64][72]  (row = kv, col = d)
//   Vth[64][72] Vtl[64][72] (row = hd, col = kv;  V transposed on load)
// ---------------------------------------------------------------------------
#define APAD 72
#define AQ_H 0
#define AQ_L (128 * APAD)
#define AK_H (2 * 128 * APAD)
#define AK_L (AK_H + 64 * APAD)
#define AV_H (AK_L + 64 * APAD)
#define AV_L (AV_H + 64 * APAD)
#define ASMEM_E (AV_L + 64 * APAD)          // 36864 elems
#define ASMEM_B (ASMEM_E * 2)               // 73728 bytes

__global__ __launch_bounds__(256, 1) void attn_mma_kernel(
    const float* __restrict__ Q, const float* __restrict__ K,
    const float* __restrict__ V, float* __restrict__ Octx)
{
    extern __shared__ __nv_bfloat16 sm[];
    const uint32_t smb = smem_u32(sm);

    const int tid  = threadIdx.x;
    const int wid  = tid >> 5, lane = tid & 31;
    const int b    = blockIdx.y >> 4;
    const int h    = blockIdx.y & 15;
    const int q0   = blockIdx.x * 128;
    const size_t hoff = (size_t)h * HDD;

    // ---- load Q tile (scaled by 1/8), hi/lo split, rows as-is
    #pragma unroll
    for (int i = 0; i < 8; i++) {
        int idx = tid + i * 256;                 // 2048 float4s
        int r = idx >> 4, c4 = (idx & 15) << 2;
        float4 v4 = *reinterpret_cast<const float4*>(
            &Q[((size_t)b * SS + q0 + r) * HIDD + hoff + c4]);
        float f[4] = {v4.x * 0.125f, v4.y * 0.125f, v4.z * 0.125f, v4.w * 0.125f};
        unsigned short hs[4], ls[4];
        #pragma unroll
        for (int j = 0; j < 4; j++) {
            __nv_bfloat16 hb = __float2bfloat16(f[j]);
            hs[j] = __bfloat16_as_ushort(hb);
            ls[j] = __bfloat16_as_ushort(__float2bfloat16(f[j] - __bfloat162float(hb)));
        }
        uint2 hu = {(uint32_t)hs[0] | ((uint32_t)hs[1] << 16),
                    (uint32_t)hs[2] | ((uint32_t)hs[3] << 16)};
        uint2 lu = {(uint32_t)ls[0] | ((uint32_t)ls[1] << 16),
                    (uint32_t)ls[2] | ((uint32_t)ls[3] << 16)};
        *reinterpret_cast<uint2*>(&sm[AQ_H + r * APAD + c4]) = hu;
        *reinterpret_cast<uint2*>(&sm[AQ_L + r * APAD + c4]) = lu;
    }

    // fragment addresses
    const uint32_t aRowOff = (uint32_t)((wid * 16 + (lane & 15)) * APAD +
                                        ((lane >> 4) << 3)) * 2;
    const uint32_t bRowOff = (uint32_t)(((lane & 7) + ((lane & 16) ? 8 : 0)) * APAD +
                                        ((lane & 8) ? 8 : 0)) * 2;

    float O[8][4];
    #pragma unroll
    for (int j = 0; j < 8; j++)
        #pragma unroll
        for (int t = 0; t < 4; t++) O[j][t] = 0.f;
    float m0 = -1e30f, m1 = -1e30f, l0 = 0.f, l1 = 0.f;

    uint32_t qh[4][4], ql[4][4];
    bool qloaded = false;

    for (int kt = 0; kt < SS / 64; kt++) {
        // ---- load K + V tiles (hi/lo; V transposed)
        const size_t kvbase = ((size_t)b * SS + (size_t)kt * 64) * HIDD + hoff;
        #pragma unroll
        for (int i = 0; i < 4; i++) {
            int idx = tid + i * 256;             // 1024 float4s
            int r = idx >> 4, c4 = (idx & 15) << 2;
            float4 k4 = *reinterpret_cast<const float4*>(
                &K[kvbase + (size_t)r * HIDD + c4]);
            float kf[4] = {k4.x, k4.y, k4.z, k4.w};
            unsigned short hs[4], ls[4];
            #pragma unroll
            for (int j = 0; j < 4; j++) {
                __nv_bfloat16 hb = __float2bfloat16(kf[j]);
                hs[j] = __bfloat16_as_ushort(hb);
                ls[j] = __bfloat16_as_ushort(__float2bfloat16(kf[j] - __bfloat162float(hb)));
            }
            uint2 hu = {(uint32_t)hs[0] | ((uint32_t)hs[1] << 16),
                        (uint32_t)hs[2] | ((uint32_t)hs[3] << 16)};
            uint2 lu = {(uint32_t)ls[0] | ((uint32_t)ls[1] << 16),
                        (uint32_t)ls[2] | ((uint32_t)ls[3] << 16)};
            *reinterpret_cast<uint2*>(&sm[AK_H + r * APAD + c4]) = hu;
            *reinterpret_cast<uint2*>(&sm[AK_L + r * APAD + c4]) = lu;

            float4 v4 = *reinterpret_cast<const float4*>(
                &V[kvbase + (size_t)r * HIDD + c4]);
            float vf[4] = {v4.x, v4.y, v4.z, v4.w};
            #pragma unroll
            for (int j = 0; j < 4; j++) {
                __nv_bfloat16 hb = __float2bfloat16(vf[j]);
                sm[AV_H + (c4 + j) * APAD + r] = hb;
                sm[AV_L + (c4 + j) * APAD + r] =
                    __float2bfloat16(vf[j] - __bfloat162float(hb));
            }
        }
        __syncthreads();

        if (!qloaded) {
            qloaded = true;
            #pragma unroll
            for (int kk = 0; kk < 4; kk++) {
                ldm4(qh[kk], smb + (uint32_t)AQ_H * 2 + aRowOff + kk * 32);
                ldm4(ql[kk], smb + (uint32_t)AQ_L * 2 + aRowOff + kk * 32);
            }
        }

        // ---- S = Q K^T (3-term)
        float sf[8][4];
        #pragma unroll
        for (int j = 0; j < 8; j++)
            #pragma unroll
            for (int t = 0; t < 4; t++) sf[j][t] = 0.f;

        #pragma unroll
        for (int kk = 0; kk < 4; kk++) {
            #pragma unroll
            for (int nb = 0; nb < 4; nb++) {
                uint32_t rh[4], rl[4];
                ldm4(rh, smb + (uint32_t)AK_H * 2 + bRowOff +
                          (uint32_t)(nb * 16 * APAD) * 2 + kk * 32);
                ldm4(rl, smb + (uint32_t)AK_L * 2 + bRowOff +
                          (uint32_t)(nb * 16 * APAD) * 2 + kk * 32);
                uint32_t bh0[2] = {rh[0], rh[1]}, bh1[2] = {rh[2], rh[3]};
                uint32_t bl0[2] = {rl[0], rl[1]}, bl1[2] = {rl[2], rl[3]};
                mma_bf16(sf[nb*2],   qh[kk], bh0);
                mma_bf16(sf[nb*2],   ql[kk], bh0);
                mma_bf16(sf[nb*2],   qh[kk], bl0);
                mma_bf16(sf[nb*2+1], qh[kk], bh1);
                mma_bf16(sf[nb*2+1], ql[kk], bh1);
                mma_bf16(sf[nb*2+1], qh[kk], bl1);
            }
        }

        // ---- online softmax (rows er and er+8; 4 lanes per row)
        float mx0 = -1e30f, mx1 = -1e30f;
        #pragma unroll
        for (int j = 0; j < 8; j++) {
            mx0 = fmaxf(mx0, fmaxf(sf[j][0], sf[j][1]));
            mx1 = fmaxf(mx1, fmaxf(sf[j][2], sf[j][3]));
        }
        mx0 = fmaxf(mx0, __shfl_xor_sync(0xffffffffu, mx0, 1));
        mx0 = fmaxf(mx0, __shfl_xor_sync(0xffffffffu, mx0, 2));
        mx1 = fmaxf(mx1, __shfl_xor_sync(0xffffffffu, mx1, 1));
        mx1 = fmaxf(mx1, __shfl_xor_sync(0xffffffffu, mx1, 2));
        float mn0 = fmaxf(m0, mx0), mn1 = fmaxf(m1, mx1);
        float c0 = __expf(m0 - mn0), c1 = __expf(m1 - mn1);
        m0 = mn0; m1 = mn1;

        float rs0 = 0.f, rs1 = 0.f;
        #pragma unroll
        for (int j = 0; j < 8; j++) {
            sf[j][0] = __expf(sf[j][0] - mn0);
            sf[j][1] = __expf(sf[j][1] - mn0);
            sf[j][2] = __expf(sf[j][2] - mn1);
            sf[j][3] = __expf(sf[j][3] - mn1);
            rs0 += sf[j][0] + sf[j][1];
            rs1 += sf[j][2] + sf[j][3];
        }
        rs0 += __shfl_xor_sync(0xffffffffu, rs0, 1);
        rs0 += __shfl_xor_sync(0xffffffffu, rs0, 2);
        rs1 += __shfl_xor_sync(0xffffffffu, rs1, 1);
        rs1 += __shfl_xor_sync(0xffffffffu, rs1, 2);
        l0 = l0 * c0 + rs0;
        l1 = l1 * c1 + rs1;

        #pragma unroll
        for (int j = 0; j < 8; j++) {
            O[j][0] *= c0; O[j][1] *= c0;
            O[j][2] *= c1; O[j][3] *= c1;
        }

        // ---- pack P hi/lo into A fragments
        uint32_t ph01[8], ph23[8], pl01[8], pl23[8];
        #pragma unroll
        for (int j = 0; j < 8; j++) {
            float p0 = sf[j][0], p1 = sf[j][1], p2 = sf[j][2], p3 = sf[j][3];
            __nv_bfloat16 h0 = __float2bfloat16(p0), h1 = __float2bfloat16(p1);
            __nv_bfloat16 h2 = __float2bfloat16(p2), h3 = __float2bfloat16(p3);
            ph01[j] = (uint32_t)__bfloat16_as_ushort(h0) |
                      ((uint32_t)__bfloat16_as_ushort(h1) << 16);
            ph23[j] = (uint32_t)__bfloat16_as_ushort(h2) |
                      ((uint32_t)__bfloat16_as_ushort(h3) << 16);
            pl01[j] = pack2bf(p0 - __bfloat162float(h0), p1 - __bfloat162float(h1));
            pl23[j] = pack2bf(p2 - __bfloat162float(h2), p3 - __bfloat162float(h3));
        }

        // ---- O += P V (3-term); A = P frags, B = Vt
        #pragma unroll
        for (int kk = 0; kk < 4; kk++) {
            uint32_t ah[4] = {ph01[2*kk], ph23[2*kk], ph01[2*kk+1], ph23[2*kk+1]};
            uint32_t al[4] = {pl01[2*kk], pl23[2*kk], pl01[2*kk+1], pl23[2*kk+1]};
            #pragma unroll
            for (int nb = 0; nb < 4; nb++) {
                uint32_t rh[4], rl[4];
                ldm4(rh, smb + (uint32_t)AV_H * 2 + bRowOff +
                          (uint32_t)(nb * 16 * APAD) * 2 + kk * 32);
                ldm4(rl, smb + (uint32_t)AV_L * 2 + bRowOff +
                          (uint32_t)(nb * 16 * APAD) * 2 + kk * 32);
                uint32_t bh0[2] = {rh[0], rh[1]}, bh1[2] = {rh[2], rh[3]};
                uint32_t bl0[2] = {rl[0], rl[1]}, bl1[2] = {rl[2], rl[3]};
                mma_bf16(O[nb*2],   ah, bh0);
                mma_bf16(O[nb*2],   al, bh0);
                mma_bf16(O[nb*2],   ah, bl0);
                mma_bf16(O[nb*2+1], ah, bh1);
                mma_bf16(O[nb*2+1], al, bh1);
                mma_bf16(O[nb*2+1], ah, bl1);
            }
        }
        __syncthreads();
    }

    // ---- epilogue
    const int er = lane >> 2, ec = (lane & 3) * 2;
    const float inv0 = 1.f / l0, inv1 = 1.f / l1;
    const int row0 = q0 + wid * 16 + er;
    #pragma unroll
    for (int j = 0; j < 8; j++) {
        const int col = (int)hoff + j * 8 + ec;
        float2 v0 = {O[j][0] * inv0, O[j][1] * inv0};
        *reinterpret_cast<float2*>(
            &Octx[((size_t)b * SS + row0) * HIDD + col]) = v0;
        float2 v1 = {O[j][2] * inv1, O[j][3] * inv1};
        *reinterpret_cast<float2*>(
            &Octx[((size_t)b * SS + row0 + 8) * HIDD + col]) = v1;
    }
}

// ---------------------------------------------------------------------------

extern "C" void kernel_launch(void* const* d_in, const int* in_sizes, int n_in,
                              void* d_out, int out_size)
{
    const float* query = (const float*)d_in[0];
    const float* key_  = (const float*)d_in[1];
    const float* value = (const float*)d_in[2];
    const float* Wq    = (const float*)d_in[3];
    const float* bq    = (const float*)d_in[4];
    const float* Wk    = (const float*)d_in[5];
    const float* bk    = (const float*)d_in[6];
    const float* Wv    = (const float*)d_in[7];
    const float* bv    = (const float*)d_in[8];
    const float* Wo    = (const float*)d_in[9];
    const float* bo    = (const float*)d_in[10];
    float* out = (float*)d_out;

    float *q, *k, *v, *c;
    __nv_bfloat16 *ahi, *alo, *wthi, *wtlo;
    cudaGetSymbolAddress((void**)&q, g_q);
    cudaGetSymbolAddress((void**)&k, g_k);
    cudaGetSymbolAddress((void**)&v, g_v);
    cudaGetSymbolAddress((void**)&c, g_c);
    cudaGetSymbolAddress((void**)&ahi, g_ahi);
    cudaGetSymbolAddress((void**)&alo, g_alo);
    cudaGetSymbolAddress((void**)&wthi, g_wthi);
    cudaGetSymbolAddress((void**)&wtlo, g_wtlo);

    cudaFuncSetAttribute(mma_gemm_kernel,
                         cudaFuncAttributeMaxDynamicSharedMemorySize, GSMEM);
    cudaFuncSetAttribute(attn_mma_kernel,
                         cudaFuncAttributeMaxDynamicSharedMemorySize, ASMEM_B);

    const int n4_act = MM * HIDD / 4;
    dim3 tgrid(HIDD / 128, MM / 128);
    dim3 trgrid(32, 32);

    split_kernel<<<n4_act / 256, 256>>>(query, ahi, alo, n4_act);
    splitT_kernel<<<trgrid, 256>>>(Wq, wthi, wtlo);
    mma_gemm_kernel<<<tgrid, 256, GSMEM>>>(ahi, alo, wthi, wtlo, bq, q);

    split_kernel<<<n4_act / 256, 256>>>(key_, ahi, alo, n4_act);
    splitT_kernel<<<trgrid, 256>>>(Wk, wthi, wtlo);
    mma_gemm_kernel<<<tgrid, 256, GSMEM>>>(ahi, alo, wthi, wtlo, bk, k);

    split_kernel<<<n4_act / 256, 256>>>(value, ahi, alo, n4_act);
    splitT_kernel<<<trgrid, 256>>>(Wv, wthi, wtlo);
    mma_gemm_kernel<<<tgrid, 256, GSMEM>>>(ahi, alo, wthi, wtlo, bv, v);

    attn_mma_kernel<<<dim3(SS / 128, BB * NHH), 256, ASMEM_B>>>(q, k, v, c);

    split_kernel<<<n4_act / 256, 256>>>(c, ahi, alo, n4_act);
    splitT_kernel<<<trgrid, 256>>>(Wo, wthi, wtlo);
    mma_gemm_kernel<<<tgrid, 256, GSMEM>>>(ahi, alo, wthi, wtlo, bo, out);
}

// round 7
// speedup vs baseline: 2.6306x; 1.1962x over previous
#include <cuda_runtime.h>
#include <cuda_bf16.h>
#include <stdint.h>
#include <math.h>

#define BB   2
#define SS   2048
#define HIDD 1024
#define NHH  16
#define HDD  64
#define MM   (BB * SS)   // 4096 rows

// ---------------------------------------------------------------------------
// Scratch (bf16 hi/lo everywhere; no fp32 intermediates)
// ---------------------------------------------------------------------------
__device__ __nv_bfloat16 g_ahi[(size_t)MM * HIDD];
__device__ __nv_bfloat16 g_alo[(size_t)MM * HIDD];
__device__ __nv_bfloat16 g_wthi[(size_t)HIDD * HIDD];
__device__ __nv_bfloat16 g_wtlo[(size_t)HIDD * HIDD];
__device__ __nv_bfloat16 g_qhi[(size_t)MM * HIDD];
__device__ __nv_bfloat16 g_qlo[(size_t)MM * HIDD];
__device__ __nv_bfloat16 g_khi[(size_t)MM * HIDD];
__device__ __nv_bfloat16 g_klo[(size_t)MM * HIDD];
__device__ __nv_bfloat16 g_vhi[(size_t)MM * HIDD];
__device__ __nv_bfloat16 g_vlo[(size_t)MM * HIDD];
__device__ __nv_bfloat16 g_chi[(size_t)MM * HIDD];
__device__ __nv_bfloat16 g_clo[(size_t)MM * HIDD];

// ---------------------------------------------------------------------------
// PTX helpers (sm_80+ portable)
// ---------------------------------------------------------------------------
__device__ __forceinline__ uint32_t smem_u32(const void* p) {
    uint32_t a;
    asm("{ .reg .u64 t; cvta.to.shared.u64 t, %1; cvt.u32.u64 %0, t; }"
        : "=r"(a) : "l"(p));
    return a;
}
__device__ __forceinline__ void cp16(uint32_t saddr, const void* g) {
    asm volatile("cp.async.cg.shared.global [%0], [%1], 16;"
                 :: "r"(saddr), "l"(g) : "memory");
}
__device__ __forceinline__ void cp_commit() {
    asm volatile("cp.async.commit_group;" ::: "memory");
}
__device__ __forceinline__ void cp_wait1() {
    asm volatile("cp.async.wait_group 1;" ::: "memory");
}
__device__ __forceinline__ void cp_wait0() {
    asm volatile("cp.async.wait_group 0;" ::: "memory");
}
__device__ __forceinline__ void ldm4(uint32_t* r, uint32_t addr) {
    asm volatile("ldmatrix.sync.aligned.m8n8.x4.shared.b16 {%0,%1,%2,%3}, [%4];"
                 : "=r"(r[0]), "=r"(r[1]), "=r"(r[2]), "=r"(r[3]) : "r"(addr));
}
__device__ __forceinline__ void ldm4t(uint32_t* r, uint32_t addr) {
    asm volatile("ldmatrix.sync.aligned.m8n8.x4.trans.shared.b16 {%0,%1,%2,%3}, [%4];"
                 : "=r"(r[0]), "=r"(r[1]), "=r"(r[2]), "=r"(r[3]) : "r"(addr));
}
__device__ __forceinline__ void mma_bf16(float* c, const uint32_t* a,
                                         const uint32_t* b) {
    asm volatile(
        "mma.sync.aligned.m16n8k16.row.col.f32.bf16.bf16.f32 "
        "{%0,%1,%2,%3}, {%4,%5,%6,%7}, {%8,%9}, {%0,%1,%2,%3};"
        : "+f"(c[0]), "+f"(c[1]), "+f"(c[2]), "+f"(c[3])
        : "r"(a[0]), "r"(a[1]), "r"(a[2]), "r"(a[3]), "r"(b[0]), "r"(b[1]));
}
__device__ __forceinline__ uint32_t pack2bf(float a, float b) {
    return (uint32_t)__bfloat16_as_ushort(__float2bfloat16(a)) |
           ((uint32_t)__bfloat16_as_ushort(__float2bfloat16(b)) << 16);
}

// ---------------------------------------------------------------------------
// fp32 -> bf16 hi/lo split (inputs only)
// ---------------------------------------------------------------------------
__global__ __launch_bounds__(256) void split_kernel(
    const float* __restrict__ x, __nv_bfloat16* __restrict__ hi,
    __nv_bfloat16* __restrict__ lo, int n4)
{
    int i = blockIdx.x * 256 + threadIdx.x;
    if (i >= n4) return;
    float4 v = reinterpret_cast<const float4*>(x)[i];
    float f[4] = {v.x, v.y, v.z, v.w};
    unsigned short hs[4], ls[4];
    #pragma unroll
    for (int j = 0; j < 4; j++) {
        __nv_bfloat16 h = __float2bfloat16(f[j]);
        __nv_bfloat16 l = __float2bfloat16(f[j] - __bfloat162float(h));
        hs[j] = __bfloat16_as_ushort(h);
        ls[j] = __bfloat16_as_ushort(l);
    }
    uint2 ho, llo;
    ho.x  = (uint32_t)hs[0] | ((uint32_t)hs[1] << 16);
    ho.y  = (uint32_t)hs[2] | ((uint32_t)hs[3] << 16);
    llo.x = (uint32_t)ls[0] | ((uint32_t)ls[1] << 16);
    llo.y = (uint32_t)ls[2] | ((uint32_t)ls[3] << 16);
    reinterpret_cast<uint2*>(hi)[i] = ho;
    reinterpret_cast<uint2*>(lo)[i] = llo;
}

// ---------------------------------------------------------------------------
// W [K][N] fp32 -> W^T [N][K] bf16 hi/lo
// ---------------------------------------------------------------------------
__global__ __launch_bounds__(256) void splitT_kernel(
    const float* __restrict__ W, __nv_bfloat16* __restrict__ Th,
    __nv_bfloat16* __restrict__ Tl)
{
    __shared__ float t[32][33];
    int n0 = blockIdx.x * 32, k0 = blockIdx.y * 32;
    int tx = threadIdx.x & 31, ty = threadIdx.x >> 5;
    #pragma unroll
    for (int i = 0; i < 4; i++)
        t[ty + i * 8][tx] = W[(size_t)(k0 + ty + i * 8) * HIDD + n0 + tx];
    __syncthreads();
    #pragma unroll
    for (int i = 0; i < 4; i++) {
        float x = t[tx][ty + i * 8];
        __nv_bfloat16 h = __float2bfloat16(x);
        __nv_bfloat16 l = __float2bfloat16(x - __bfloat162float(h));
        size_t o = (size_t)(n0 + ty + i * 8) * HIDD + k0 + tx;
        Th[o] = h;
        Tl[o] = l;
    }
}

// ---------------------------------------------------------------------------
// HMMA 3x-emulated GEMM: C = A @ W + bias.
// mode 0: write fp32 to Cf.   mode 1: write (acc+bias)*scale split hi/lo.
// ---------------------------------------------------------------------------
#define TPAD 40
#define TILE_E (128 * TPAD)
#define TILE_B (TILE_E * 2)
#define STAGE_B (4 * TILE_B)
#define GSMEM (2 * STAGE_B)
#define NCHUNK (HIDD / 32)

__global__ __launch_bounds__(256, 1) void mma_gemm_kernel(
    const __nv_bfloat16* __restrict__ Ahi, const __nv_bfloat16* __restrict__ Alo,
    const __nv_bfloat16* __restrict__ Bth, const __nv_bfloat16* __restrict__ Btl,
    const float* __restrict__ bias, float* __restrict__ Cf,
    __nv_bfloat16* __restrict__ Chi, __nv_bfloat16* __restrict__ Clo,
    int mode, float scale)
{
    extern __shared__ __nv_bfloat16 sm[];
    const uint32_t smb = smem_u32(sm);

    const int tid  = threadIdx.x;
    const int wid  = tid >> 5, lane = tid & 31;
    const int m0   = blockIdx.y * 128, n0 = blockIdx.x * 128;
    const int wm   = (wid >> 1) * 32;
    const int wn   = (wid & 1) * 64;

    const int lrow = tid >> 1;
    const int lcol = (tid & 1) * 16;
    const size_t gA = (size_t)(m0 + lrow) * HIDD + lcol;
    const size_t gB = (size_t)(n0 + lrow) * HIDD + lcol;
    const uint32_t sO = smb + (uint32_t)(lrow * TPAD + lcol) * 2;

    float acc[2][8][4];
    #pragma unroll
    for (int im = 0; im < 2; im++)
        #pragma unroll
        for (int in = 0; in < 8; in++)
            #pragma unroll
            for (int j = 0; j < 4; j++) acc[im][in][j] = 0.f;

    const int a_row = wm + (lane & 15);
    const int a_col = (lane >> 4) << 3;
    const int b_row = wn + (lane & 7) + ((lane & 16) ? 8 : 0);
    const int b_col = (lane & 8) ? 8 : 0;
    const uint32_t aOff = (uint32_t)(a_row * TPAD + a_col) * 2;
    const uint32_t bOff = (uint32_t)(b_row * TPAD + b_col) * 2;

    {
        uint32_t so = sO;
        cp16(so,              Ahi + gA); cp16(so + 16,              Ahi + gA + 8);
        cp16(so + TILE_B,     Alo + gA); cp16(so + TILE_B + 16,     Alo + gA + 8);
        cp16(so + 2*TILE_B,   Bth + gB); cp16(so + 2*TILE_B + 16,   Bth + gB + 8);
        cp16(so + 3*TILE_B,   Btl + gB); cp16(so + 3*TILE_B + 16,   Btl + gB + 8);
        cp_commit();
    }

    for (int kc = 0; kc < NCHUNK; kc++) {
        const int s = kc & 1;
        if (kc + 1 < NCHUNK) {
            uint32_t so = sO + (s ^ 1) * STAGE_B;
            size_t ga = gA + (kc + 1) * 32, gb = gB + (kc + 1) * 32;
            cp16(so,              Ahi + ga); cp16(so + 16,              Ahi + ga + 8);
            cp16(so + TILE_B,     Alo + ga); cp16(so + TILE_B + 16,     Alo + ga + 8);
            cp16(so + 2*TILE_B,   Bth + gb); cp16(so + 2*TILE_B + 16,   Bth + gb + 8);
            cp16(so + 3*TILE_B,   Btl + gb); cp16(so + 3*TILE_B + 16,   Btl + gb + 8);
            cp_commit();
            cp_wait1();
        } else {
            cp_wait0();
        }
        __syncthreads();

        const uint32_t st = smb + s * STAGE_B;
        #pragma unroll
        for (int ks = 0; ks < 32; ks += 16) {
            uint32_t aH[2][4], aL[2][4], bH[8][2], bL[8][2];
            #pragma unroll
            for (int im = 0; im < 2; im++) {
                ldm4(aH[im], st + aOff + (uint32_t)(im * 16 * TPAD + ks) * 2);
                ldm4(aL[im], st + TILE_B + aOff + (uint32_t)(im * 16 * TPAD + ks) * 2);
            }
            #pragma unroll
            for (int ib = 0; ib < 4; ib++) {
                uint32_t r[4];
                ldm4(r, st + 2*TILE_B + bOff + (uint32_t)(ib * 16 * TPAD + ks) * 2);
                bH[ib*2][0] = r[0]; bH[ib*2][1] = r[1];
                bH[ib*2+1][0] = r[2]; bH[ib*2+1][1] = r[3];
                ldm4(r, st + 3*TILE_B + bOff + (uint32_t)(ib * 16 * TPAD + ks) * 2);
                bL[ib*2][0] = r[0]; bL[ib*2][1] = r[1];
                bL[ib*2+1][0] = r[2]; bL[ib*2+1][1] = r[3];
            }
            #pragma unroll
            for (int im = 0; im < 2; im++)
                #pragma unroll
                for (int in = 0; in < 8; in++) {
                    mma_bf16(acc[im][in], aH[im], bH[in]);
                    mma_bf16(acc[im][in], aL[im], bH[in]);
                    mma_bf16(acc[im][in], aH[im], bL[in]);
                }
        }
        __syncthreads();
    }

    const int er = lane >> 2, ec = (lane & 3) * 2;
    if (mode == 0) {
        #pragma unroll
        for (int im = 0; im < 2; im++)
            #pragma unroll
            for (int in = 0; in < 8; in++) {
                const int n = n0 + wn + in * 8 + ec;
                const float bx = bias[n], by = bias[n + 1];
                const int mA = m0 + wm + im * 16 + er;
                float2 v0 = {acc[im][in][0] + bx, acc[im][in][1] + by};
                *reinterpret_cast<float2*>(Cf + (size_t)mA * HIDD + n) = v0;
                float2 v1 = {acc[im][in][2] + bx, acc[im][in][3] + by};
                *reinterpret_cast<float2*>(Cf + (size_t)(mA + 8) * HIDD + n) = v1;
            }
    } else {
        uint32_t* chiu = reinterpret_cast<uint32_t*>(Chi);
        uint32_t* clou = reinterpret_cast<uint32_t*>(Clo);
        #pragma unroll
        for (int im = 0; im < 2; im++)
            #pragma unroll
            for (int in = 0; in < 8; in++) {
                const int n = n0 + wn + in * 8 + ec;
                const float bx = bias[n], by = bias[n + 1];
                const int mA = m0 + wm + im * 16 + er;
                float f0 = (acc[im][in][0] + bx) * scale;
                float f1 = (acc[im][in][1] + by) * scale;
                float f2 = (acc[im][in][2] + bx) * scale;
                float f3 = (acc[im][in][3] + by) * scale;
                __nv_bfloat16 h0 = __float2bfloat16(f0), h1 = __float2bfloat16(f1);
                __nv_bfloat16 h2 = __float2bfloat16(f2), h3 = __float2bfloat16(f3);
                size_t i0 = ((size_t)mA * HIDD + n) >> 1;
                size_t i1 = ((size_t)(mA + 8) * HIDD + n) >> 1;
                chiu[i0] = (uint32_t)__bfloat16_as_ushort(h0) |
                           ((uint32_t)__bfloat16_as_ushort(h1) << 16);
                chiu[i1] = (uint32_t)__bfloat16_as_ushort(h2) |
                           ((uint32_t)__bfloat16_as_ushort(h3) << 16);
                clou[i0] = pack2bf(f0 - __bfloat162float(h0), f1 - __bfloat162float(h1));
                clou[i1] = pack2bf(f2 - __bfloat162float(h2), f3 - __bfloat162float(h3));
            }
    }
}

// ---------------------------------------------------------------------------
// HMMA flash attention, all operands presplit bf16 hi/lo.
// Block = (b, h, 128 q rows), 8 warps. KV tile 64, cp.async double buffered.
// K and V tiles both [kv][d]; V's B-fragment comes from ldmatrix.trans.
// ---------------------------------------------------------------------------
#define APAD 72
#define SQ_H 0
#define SQ_L (128 * APAD)
#define SKV  (2 * 128 * APAD)
#define KV_K_L (64 * APAD)
#define KV_V_H (2 * 64 * APAD)
#define KV_V_L (3 * 64 * APAD)
#define KV_STG (4 * 64 * APAD)
#define ASMEM_E (SKV + 2 * KV_STG)
#define ASMEM_B (ASMEM_E * 2)              // 110592 bytes

__global__ __launch_bounds__(256, 1) void attn_mma_kernel(
    const __nv_bfloat16* __restrict__ qhi, const __nv_bfloat16* __restrict__ qlo,
    const __nv_bfloat16* __restrict__ khi, const __nv_bfloat16* __restrict__ klo,
    const __nv_bfloat16* __restrict__ vhi, const __nv_bfloat16* __restrict__ vlo,
    __nv_bfloat16* __restrict__ chi, __nv_bfloat16* __restrict__ clo)
{
    extern __shared__ __nv_bfloat16 sm[];
    const uint32_t smb = smem_u32(sm);

    const int tid  = threadIdx.x;
    const int wid  = tid >> 5, lane = tid & 31;
    const int b    = blockIdx.y >> 4;
    const int h    = blockIdx.y & 15;
    const int q0   = blockIdx.x * 128;
    const int hoff = h * HDD;

    // ---- Q tile via cp.async (its own commit group)
    {
        const size_t qg = ((size_t)b * SS + q0) * HIDD + hoff;
        #pragma unroll
        for (int i = 0; i < 4; i++) {
            int idx = tid + i * 256;            // 1024: 128 rows x 8 chunks
            int r = idx >> 3, ch = idx & 7;
            cp16(smb + (uint32_t)(SQ_H + r * APAD + ch * 8) * 2,
                 qhi + qg + (size_t)r * HIDD + ch * 8);
            cp16(smb + (uint32_t)(SQ_L + r * APAD + ch * 8) * 2,
                 qlo + qg + (size_t)r * HIDD + ch * 8);
        }
        cp_commit();
    }

    auto issue_kv = [&](int s, int kt) {
        const uint32_t sb = smb + (uint32_t)(SKV + s * KV_STG) * 2;
        #pragma unroll
        for (int i = 0; i < 2; i++) {
            int idx = tid + i * 256;            // 512: 64 rows x 8 chunks
            int r = idx >> 3, ch = idx & 7;
            size_t g = ((size_t)b * SS + kt * 64 + r) * HIDD + hoff + ch * 8;
            uint32_t so = sb + (uint32_t)(r * APAD + ch * 8) * 2;
            cp16(so,                          khi + g);
            cp16(so + (uint32_t)KV_K_L * 2,   klo + g);
            cp16(so + (uint32_t)KV_V_H * 2,   vhi + g);
            cp16(so + (uint32_t)KV_V_L * 2,   vlo + g);
        }
        cp_commit();
    };
    issue_kv(0, 0);

    // fragment lane offsets
    const uint32_t aRowOff = (uint32_t)((wid * 16 + (lane & 15)) * APAD +
                                        ((lane >> 4) << 3)) * 2;
    const uint32_t bRowOff = (uint32_t)(((lane & 7) + ((lane & 16) ? 8 : 0)) * APAD +
                                        ((lane & 8) ? 8 : 0)) * 2;
    const uint32_t vRowOff = (uint32_t)((lane & 15) * APAD +
                                        ((lane >> 4) << 3)) * 2;

    float O[8][4];
    #pragma unroll
    for (int j = 0; j < 8; j++)
        #pragma unroll
        for (int t = 0; t < 4; t++) O[j][t] = 0.f;
    float m0 = -1e30f, m1 = -1e30f, l0 = 0.f, l1 = 0.f;
    uint32_t qh[4][4], ql[4][4];

    for (int kt = 0; kt < SS / 64; kt++) {
        const int s = kt & 1;
        if (kt + 1 < SS / 64) {
            issue_kv(s ^ 1, kt + 1);
            cp_wait1();
        } else {
            cp_wait0();
        }
        __syncthreads();

        if (kt == 0) {
            #pragma unroll
            for (int kk = 0; kk < 4; kk++) {
                ldm4(qh[kk], smb + (uint32_t)SQ_H * 2 + aRowOff + kk * 32);
                ldm4(ql[kk], smb + (uint32_t)SQ_L * 2 + aRowOff + kk * 32);
            }
        }

        const uint32_t kvb = smb + (uint32_t)(SKV + s * KV_STG) * 2;

        // ---- S = Q K^T (3-term)
        float sf[8][4];
        #pragma unroll
        for (int j = 0; j < 8; j++)
            #pragma unroll
            for (int t = 0; t < 4; t++) sf[j][t] = 0.f;

        #pragma unroll
        for (int kk = 0; kk < 4; kk++) {
            #pragma unroll
            for (int nb = 0; nb < 4; nb++) {
                uint32_t rh[4], rl[4];
                ldm4(rh, kvb + bRowOff + (uint32_t)(nb * 16 * APAD) * 2 + kk * 32);
                ldm4(rl, kvb + (uint32_t)KV_K_L * 2 + bRowOff +
                          (uint32_t)(nb * 16 * APAD) * 2 + kk * 32);
                uint32_t bh0[2] = {rh[0], rh[1]}, bh1[2] = {rh[2], rh[3]};
                uint32_t bl0[2] = {rl[0], rl[1]}, bl1[2] = {rl[2], rl[3]};
                mma_bf16(sf[nb*2],   qh[kk], bh0);
                mma_bf16(sf[nb*2],   ql[kk], bh0);
                mma_bf16(sf[nb*2],   qh[kk], bl0);
                mma_bf16(sf[nb*2+1], qh[kk], bh1);
                mma_bf16(sf[nb*2+1], ql[kk], bh1);
                mma_bf16(sf[nb*2+1], qh[kk], bl1);
            }
        }

        // ---- online softmax
        float mx0 = -1e30f, mx1 = -1e30f;
        #pragma unroll
        for (int j = 0; j < 8; j++) {
            mx0 = fmaxf(mx0, fmaxf(sf[j][0], sf[j][1]));
            mx1 = fmaxf(mx1, fmaxf(sf[j][2], sf[j][3]));
        }
        mx0 = fmaxf(mx0, __shfl_xor_sync(0xffffffffu, mx0, 1));
        mx0 = fmaxf(mx0, __shfl_xor_sync(0xffffffffu, mx0, 2));
        mx1 = fmaxf(mx1, __shfl_xor_sync(0xffffffffu, mx1, 1));
        mx1 = fmaxf(mx1, __shfl_xor_sync(0xffffffffu, mx1, 2));
        float mn0 = fmaxf(m0, mx0), mn1 = fmaxf(m1, mx1);
        float c0 = __expf(m0 - mn0), c1 = __expf(m1 - mn1);
        m0 = mn0; m1 = mn1;

        float rs0 = 0.f, rs1 = 0.f;
        #pragma unroll
        for (int j = 0; j < 8; j++) {
            sf[j][0] = __expf(sf[j][0] - mn0);
            sf[j][1] = __expf(sf[j][1] - mn0);
            sf[j][2] = __expf(sf[j][2] - mn1);
            sf[j][3] = __expf(sf[j][3] - mn1);
            rs0 += sf[j][0] + sf[j][1];
            rs1 += sf[j][2] + sf[j][3];
        }
        rs0 += __shfl_xor_sync(0xffffffffu, rs0, 1);
        rs0 += __shfl_xor_sync(0xffffffffu, rs0, 2);
        rs1 += __shfl_xor_sync(0xffffffffu, rs1, 1);
        rs1 += __shfl_xor_sync(0xffffffffu, rs1, 2);
        l0 = l0 * c0 + rs0;
        l1 = l1 * c1 + rs1;

        #pragma unroll
        for (int j = 0; j < 8; j++) {
            O[j][0] *= c0; O[j][1] *= c0;
            O[j][2] *= c1; O[j][3] *= c1;
        }

        // ---- pack P hi/lo into A fragments
        uint32_t ph01[8], ph23[8], pl01[8], pl23[8];
        #pragma unroll
        for (int j = 0; j < 8; j++) {
            float p0 = sf[j][0], p1 = sf[j][1], p2 = sf[j][2], p3 = sf[j][3];
            __nv_bfloat16 h0 = __float2bfloat16(p0), h1 = __float2bfloat16(p1);
            __nv_bfloat16 h2 = __float2bfloat16(p2), h3 = __float2bfloat16(p3);
            ph01[j] = (uint32_t)__bfloat16_as_ushort(h0) |
                      ((uint32_t)__bfloat16_as_ushort(h1) << 16);
            ph23[j] = (uint32_t)__bfloat16_as_ushort(h2) |
                      ((uint32_t)__bfloat16_as_ushort(h3) << 16);
            pl01[j] = pack2bf(p0 - __bfloat162float(h0), p1 - __bfloat162float(h1));
            pl23[j] = pack2bf(p2 - __bfloat162float(h2), p3 - __bfloat162float(h3));
        }

        // ---- O += P V (3-term); V [kv][d] read via ldmatrix.trans
        #pragma unroll
        for (int kk = 0; kk < 4; kk++) {
            uint32_t ah[4] = {ph01[2*kk], ph23[2*kk], ph01[2*kk+1], ph23[2*kk+1]};
            uint32_t al[4] = {pl01[2*kk], pl23[2*kk], pl01[2*kk+1], pl23[2*kk+1]};
            #pragma unroll
            for (int nb = 0; nb < 4; nb++) {
                uint32_t rh[4], rl[4];
                uint32_t voff = vRowOff + (uint32_t)(kk * 16 * APAD + nb * 16) * 2;
                ldm4t(rh, kvb + (uint32_t)KV_V_H * 2 + voff);
                ldm4t(rl, kvb + (uint32_t)KV_V_L * 2 + voff);
                uint32_t bh0[2] = {rh[0], rh[1]}, bh1[2] = {rh[2], rh[3]};
                uint32_t bl0[2] = {rl[0], rl[1]}, bl1[2] = {rl[2], rl[3]};
                mma_bf16(O[nb*2],   ah, bh0);
                mma_bf16(O[nb*2],   al, bh0);
                mma_bf16(O[nb*2],   ah, bl0);
                mma_bf16(O[nb*2+1], ah, bh1);
                mma_bf16(O[nb*2+1], al, bh1);
                mma_bf16(O[nb*2+1], ah, bl1);
            }
        }
        __syncthreads();
    }

    // ---- epilogue: ctx as bf16 hi/lo for the O projection
    const int er = lane >> 2, ec = (lane & 3) * 2;
    const float inv0 = 1.f / l0, inv1 = 1.f / l1;
    const int row0 = q0 + wid * 16 + er;
    uint32_t* chiu = reinterpret_cast<uint32_t*>(chi);
    uint32_t* clou = reinterpret_cast<uint32_t*>(clo);
    #pragma unroll
    for (int j = 0; j < 8; j++) {
        const int col = hoff + j * 8 + ec;
        float f0 = O[j][0] * inv0, f1 = O[j][1] * inv0;
        float f2 = O[j][2] * inv1, f3 = O[j][3] * inv1;
        __nv_bfloat16 h0 = __float2bfloat16(f0), h1 = __float2bfloat16(f1);
        __nv_bfloat16 h2 = __float2bfloat16(f2), h3 = __float2bfloat16(f3);
        size_t i0 = (((size_t)b * SS + row0) * HIDD + col) >> 1;
        size_t i1 = (((size_t)b * SS + row0 + 8) * HIDD + col) >> 1;
        chiu[i0] = (uint32_t)__bfloat16_as_ushort(h0) |
                   ((uint32_t)__bfloat16_as_ushort(h1) << 16);
        chiu[i1] = (uint32_t)__bfloat16_as_ushort(h2) |
                   ((uint32_t)__bfloat16_as_ushort(h3) << 16);
        clou[i0] = pack2bf(f0 - __bfloat162float(h0), f1 - __bfloat162float(h1));
        clou[i1] = pack2bf(f2 - __bfloat162float(h2), f3 - __bfloat162float(h3));
    }
}

// ---------------------------------------------------------------------------

extern "C" void kernel_launch(void* const* d_in, const int* in_sizes, int n_in,
                              void* d_out, int out_size)
{
    const float* query = (const float*)d_in[0];
    const float* key_  = (const float*)d_in[1];
    const float* value = (const float*)d_in[2];
    const float* Wq    = (const float*)d_in[3];
    const float* bq    = (const float*)d_in[4];
    const float* Wk    = (const float*)d_in[5];
    const float* bk    = (const float*)d_in[6];
    const float* Wv    = (const float*)d_in[7];
    const float* bv    = (const float*)d_in[8];
    const float* Wo    = (const float*)d_in[9];
    const float* bo    = (const float*)d_in[10];
    float* out = (float*)d_out;

    __nv_bfloat16 *ahi, *alo, *wthi, *wtlo;
    __nv_bfloat16 *qhi, *qlo, *khi, *klo, *vhi, *vlo, *chi, *clo;
    cudaGetSymbolAddress((void**)&ahi, g_ahi);
    cudaGetSymbolAddress((void**)&alo, g_alo);
    cudaGetSymbolAddress((void**)&wthi, g_wthi);
    cudaGetSymbolAddress((void**)&wtlo, g_wtlo);
    cudaGetSymbolAddress((void**)&qhi, g_qhi);
    cudaGetSymbolAddress((void**)&qlo, g_qlo);
    cudaGetSymbolAddress((void**)&khi, g_khi);
    cudaGetSymbolAddress((void**)&klo, g_klo);
    cudaGetSymbolAddress((void**)&vhi, g_vhi);
    cudaGetSymbolAddress((void**)&vlo, g_vlo);
    cudaGetSymbolAddress((void**)&chi, g_chi);
    cudaGetSymbolAddress((void**)&clo, g_clo);

    cudaFuncSetAttribute(mma_gemm_kernel,
                         cudaFuncAttributeMaxDynamicSharedMemorySize, GSMEM);
    cudaFuncSetAttribute(attn_mma_kernel,
                         cudaFuncAttributeMaxDynamicSharedMemorySize, ASMEM_B);

    const int n4_act = MM * HIDD / 4;
    dim3 tgrid(HIDD / 128, MM / 128);
    dim3 trgrid(32, 32);

    // Q projection (scale 1/8 folded into epilogue)
    split_kernel<<<n4_act / 256, 256>>>(query, ahi, alo, n4_act);
    splitT_kernel<<<trgrid, 256>>>(Wq, wthi, wtlo);
    mma_gemm_kernel<<<tgrid, 256, GSMEM>>>(ahi, alo, wthi, wtlo, bq,
                                           nullptr, qhi, qlo, 1, 0.125f);
    // K projection
    split_kernel<<<n4_act / 256, 256>>>(key_, ahi, alo, n4_act);
    splitT_kernel<<<trgrid, 256>>>(Wk, wthi, wtlo);
    mma_gemm_kernel<<<tgrid, 256, GSMEM>>>(ahi, alo, wthi, wtlo, bk,
                                           nullptr, khi, klo, 1, 1.0f);
    // V projection
    split_kernel<<<n4_act / 256, 256>>>(value, ahi, alo, n4_act);
    splitT_kernel<<<trgrid, 256>>>(Wv, wthi, wtlo);
    mma_gemm_kernel<<<tgrid, 256, GSMEM>>>(ahi, alo, wthi, wtlo, bv,
                                           nullptr, vhi, vlo, 1, 1.0f);

    // Attention (all-MMA, presplit operands)
    attn_mma_kernel<<<dim3(SS / 128, BB * NHH), 256, ASMEM_B>>>(
        qhi, qlo, khi, klo, vhi, vlo, chi, clo);

    // Output projection (fp32 out)
    splitT_kernel<<<trgrid, 256>>>(Wo, wthi, wtlo);
    mma_gemm_kernel<<<tgrid, 256, GSMEM>>>(chi, clo, wthi, wtlo, bo,
                                           out, nullptr, nullptr, 0, 1.0f);
}

// round 8
// speedup vs baseline: 2.7094x; 1.0299x over previous
#include <cuda_runtime.h>
#include <cuda_bf16.h>
#include <stdint.h>
#include <math.h>

#define BB   2
#define SS   2048
#define HIDD 1024
#define NHH  16
#define HDD  64
#define MM   (BB * SS)   // 4096 rows

static constexpr size_t MH = (size_t)MM * HIDD;
static constexpr size_t HH = (size_t)HIDD * HIDD;

// ---------------------------------------------------------------------------
// Scratch (bf16 hi/lo everywhere)
// ---------------------------------------------------------------------------
__device__ __nv_bfloat16 g_inhi[3 * MH];   // split inputs  (q,k,v order)
__device__ __nv_bfloat16 g_inlo[3 * MH];
__device__ __nv_bfloat16 g_wthi[4 * HH];   // W^T hi (Wq,Wk,Wv,Wo)
__device__ __nv_bfloat16 g_wtlo[4 * HH];
__device__ __nv_bfloat16 g_phi[3 * MH];    // projected Q,K,V hi
__device__ __nv_bfloat16 g_plo[3 * MH];
__device__ __nv_bfloat16 g_chi[MH];        // attention ctx hi/lo
__device__ __nv_bfloat16 g_clo[MH];

// ---------------------------------------------------------------------------
// PTX helpers (sm_80+ portable)
// ---------------------------------------------------------------------------
__device__ __forceinline__ uint32_t smem_u32(const void* p) {
    uint32_t a;
    asm("{ .reg .u64 t; cvta.to.shared.u64 t, %1; cvt.u32.u64 %0, t; }"
        : "=r"(a) : "l"(p));
    return a;
}
__device__ __forceinline__ void cp16(uint32_t saddr, const void* g) {
    asm volatile("cp.async.cg.shared.global [%0], [%1], 16;"
                 :: "r"(saddr), "l"(g) : "memory");
}
__device__ __forceinline__ void cp_commit() {
    asm volatile("cp.async.commit_group;" ::: "memory");
}
__device__ __forceinline__ void cp_wait2() {
    asm volatile("cp.async.wait_group 2;" ::: "memory");
}
__device__ __forceinline__ void cp_wait1() {
    asm volatile("cp.async.wait_group 1;" ::: "memory");
}
__device__ __forceinline__ void cp_wait0() {
    asm volatile("cp.async.wait_group 0;" ::: "memory");
}
__device__ __forceinline__ void ldm4(uint32_t* r, uint32_t addr) {
    asm volatile("ldmatrix.sync.aligned.m8n8.x4.shared.b16 {%0,%1,%2,%3}, [%4];"
                 : "=r"(r[0]), "=r"(r[1]), "=r"(r[2]), "=r"(r[3]) : "r"(addr));
}
__device__ __forceinline__ void ldm4t(uint32_t* r, uint32_t addr) {
    asm volatile("ldmatrix.sync.aligned.m8n8.x4.trans.shared.b16 {%0,%1,%2,%3}, [%4];"
                 : "=r"(r[0]), "=r"(r[1]), "=r"(r[2]), "=r"(r[3]) : "r"(addr));
}
__device__ __forceinline__ void mma_bf16(float* c, const uint32_t* a,
                                         const uint32_t* b) {
    asm volatile(
        "mma.sync.aligned.m16n8k16.row.col.f32.bf16.bf16.f32 "
        "{%0,%1,%2,%3}, {%4,%5,%6,%7}, {%8,%9}, {%0,%1,%2,%3};"
        : "+f"(c[0]), "+f"(c[1]), "+f"(c[2]), "+f"(c[3])
        : "r"(a[0]), "r"(a[1]), "r"(a[2]), "r"(a[3]), "r"(b[0]), "r"(b[1]));
}
__device__ __forceinline__ uint32_t pack2bf(float a, float b) {
    return (uint32_t)__bfloat16_as_ushort(__float2bfloat16(a)) |
           ((uint32_t)__bfloat16_as_ushort(__float2bfloat16(b)) << 16);
}

// ---------------------------------------------------------------------------
// Batched fp32 -> bf16 hi/lo split (3 inputs via grid.y)
// ---------------------------------------------------------------------------
__global__ __launch_bounds__(256) void split3_kernel(
    const float* __restrict__ x0, const float* __restrict__ x1,
    const float* __restrict__ x2, __nv_bfloat16* __restrict__ hiB,
    __nv_bfloat16* __restrict__ loB, int n4)
{
    int i = blockIdx.x * 256 + threadIdx.x;
    if (i >= n4) return;
    const int z = blockIdx.y;
    const float* x = (z == 0) ? x0 : (z == 1) ? x1 : x2;
    float4 v = reinterpret_cast<const float4*>(x)[i];
    float f[4] = {v.x, v.y, v.z, v.w};
    unsigned short hs[4], ls[4];
    #pragma unroll
    for (int j = 0; j < 4; j++) {
        __nv_bfloat16 h = __float2bfloat16(f[j]);
        __nv_bfloat16 l = __float2bfloat16(f[j] - __bfloat162float(h));
        hs[j] = __bfloat16_as_ushort(h);
        ls[j] = __bfloat16_as_ushort(l);
    }
    uint2 ho, llo;
    ho.x  = (uint32_t)hs[0] | ((uint32_t)hs[1] << 16);
    ho.y  = (uint32_t)hs[2] | ((uint32_t)hs[3] << 16);
    llo.x = (uint32_t)ls[0] | ((uint32_t)ls[1] << 16);
    llo.y = (uint32_t)ls[2] | ((uint32_t)ls[3] << 16);
    size_t base = (size_t)z * (MH / 4);
    reinterpret_cast<uint2*>(hiB)[base + i] = ho;
    reinterpret_cast<uint2*>(loB)[base + i] = llo;
}

// ---------------------------------------------------------------------------
// Batched W [K][N] fp32 -> W^T [N][K] bf16 hi/lo (4 weights via grid.z)
// ---------------------------------------------------------------------------
__global__ __launch_bounds__(256) void splitT4_kernel(
    const float* __restrict__ W0, const float* __restrict__ W1,
    const float* __restrict__ W2, const float* __restrict__ W3,
    __nv_bfloat16* __restrict__ ThB, __nv_bfloat16* __restrict__ TlB)
{
    __shared__ float t[32][33];
    const int z = blockIdx.z;
    const float* W = (z == 0) ? W0 : (z == 1) ? W1 : (z == 2) ? W2 : W3;
    __nv_bfloat16* Th = ThB + (size_t)z * HH;
    __nv_bfloat16* Tl = TlB + (size_t)z * HH;
    int n0 = blockIdx.x * 32, k0 = blockIdx.y * 32;
    int tx = threadIdx.x & 31, ty = threadIdx.x >> 5;
    #pragma unroll
    for (int i = 0; i < 4; i++)
        t[ty + i * 8][tx] = W[(size_t)(k0 + ty + i * 8) * HIDD + n0 + tx];
    __syncthreads();
    #pragma unroll
    for (int i = 0; i < 4; i++) {
        float x = t[tx][ty + i * 8];
        __nv_bfloat16 h = __float2bfloat16(x);
        __nv_bfloat16 l = __float2bfloat16(x - __bfloat162float(h));
        size_t o = (size_t)(n0 + ty + i * 8) * HIDD + k0 + tx;
        Th[o] = h;
        Tl[o] = l;
    }
}

// ---------------------------------------------------------------------------
// HMMA 3x-emulated GEMM, 4-stage cp.async ring (ONE barrier per chunk).
// grid.z selects batch slice via strides. mode 0: fp32 out. mode 1: hi/lo out.
// ---------------------------------------------------------------------------
#define TPAD 40
#define TILE_E (128 * TPAD)
#define TILE_B (TILE_E * 2)        // 10240
#define STAGE_B (4 * TILE_B)       // 40960
#define GSMEM (4 * STAGE_B)        // 163840
#define NCHUNK (HIDD / 32)         // 32

__global__ __launch_bounds__(256, 1) void mma_gemm_kernel(
    const __nv_bfloat16* __restrict__ AhiB, const __nv_bfloat16* __restrict__ AloB,
    const __nv_bfloat16* __restrict__ BthB, const __nv_bfloat16* __restrict__ BtlB,
    const float* __restrict__ b0, const float* __restrict__ b1,
    const float* __restrict__ b2,
    float* __restrict__ Cf, __nv_bfloat16* __restrict__ ChiB,
    __nv_bfloat16* __restrict__ CloB, int mode, float scaleQ)
{
    extern __shared__ __nv_bfloat16 sm[];
    const uint32_t smb = smem_u32(sm);

    const int tid  = threadIdx.x;
    const int wid  = tid >> 5, lane = tid & 31;
    const int z    = blockIdx.z;
    const int m0   = blockIdx.y * 128, n0 = blockIdx.x * 128;
    const int wm   = (wid >> 1) * 32;
    const int wn   = (wid & 1) * 64;

    const __nv_bfloat16* Ahi = AhiB + (size_t)z * MH;
    const __nv_bfloat16* Alo = AloB + (size_t)z * MH;
    const __nv_bfloat16* Bth = BthB + (size_t)z * HH;
    const __nv_bfloat16* Btl = BtlB + (size_t)z * HH;
    const float* bias = (z == 0) ? b0 : (z == 1) ? b1 : b2;
    const float scale = (z == 0) ? scaleQ : 1.0f;

    const int lrow = tid >> 1;
    const int lcol = (tid & 1) * 16;
    const size_t gA = (size_t)(m0 + lrow) * HIDD + lcol;
    const size_t gB = (size_t)(n0 + lrow) * HIDD + lcol;
    const uint32_t sO = smb + (uint32_t)(lrow * TPAD + lcol) * 2;

    float acc[2][8][4];
    #pragma unroll
    for (int im = 0; im < 2; im++)
        #pragma unroll
        for (int in = 0; in < 8; in++)
            #pragma unroll
            for (int j = 0; j < 4; j++) acc[im][in][j] = 0.f;

    const int a_row = wm + (lane & 15);
    const int a_col = (lane >> 4) << 3;
    const int b_row = wn + (lane & 7) + ((lane & 16) ? 8 : 0);
    const int b_col = (lane & 8) ? 8 : 0;
    const uint32_t aOff = (uint32_t)(a_row * TPAD + a_col) * 2;
    const uint32_t bOff = (uint32_t)(b_row * TPAD + b_col) * 2;

    auto issue = [&](int kc) {
        uint32_t so = sO + (uint32_t)(kc & 3) * STAGE_B;
        size_t ga = gA + (size_t)kc * 32, gb = gB + (size_t)kc * 32;
        cp16(so,              Ahi + ga); cp16(so + 16,              Ahi + ga + 8);
        cp16(so + TILE_B,     Alo + ga); cp16(so + TILE_B + 16,     Alo + ga + 8);
        cp16(so + 2*TILE_B,   Bth + gb); cp16(so + 2*TILE_B + 16,   Bth + gb + 8);
        cp16(so + 3*TILE_B,   Btl + gb); cp16(so + 3*TILE_B + 16,   Btl + gb + 8);
        cp_commit();
    };
    issue(0); issue(1); issue(2);

    for (int kc = 0; kc < NCHUNK; kc++) {
        if (kc <= NCHUNK - 3)      cp_wait2();
        else if (kc == NCHUNK - 2) cp_wait1();
        else                       cp_wait0();
        __syncthreads();
        if (kc + 3 < NCHUNK) issue(kc + 3);

        const uint32_t st = smb + (uint32_t)(kc & 3) * STAGE_B;
        #pragma unroll
        for (int ks = 0; ks < 32; ks += 16) {
            uint32_t aH[2][4], aL[2][4], bH[8][2], bL[8][2];
            #pragma unroll
            for (int im = 0; im < 2; im++) {
                ldm4(aH[im], st + aOff + (uint32_t)(im * 16 * TPAD + ks) * 2);
                ldm4(aL[im], st + TILE_B + aOff + (uint32_t)(im * 16 * TPAD + ks) * 2);
            }
            #pragma unroll
            for (int ib = 0; ib < 4; ib++) {
                uint32_t r[4];
                ldm4(r, st + 2*TILE_B + bOff + (uint32_t)(ib * 16 * TPAD + ks) * 2);
                bH[ib*2][0] = r[0]; bH[ib*2][1] = r[1];
                bH[ib*2+1][0] = r[2]; bH[ib*2+1][1] = r[3];
                ldm4(r, st + 3*TILE_B + bOff + (uint32_t)(ib * 16 * TPAD + ks) * 2);
                bL[ib*2][0] = r[0]; bL[ib*2][1] = r[1];
                bL[ib*2+1][0] = r[2]; bL[ib*2+1][1] = r[3];
            }
            #pragma unroll
            for (int im = 0; im < 2; im++)
                #pragma unroll
                for (int in = 0; in < 8; in++) {
                    mma_bf16(acc[im][in], aH[im], bH[in]);
                    mma_bf16(acc[im][in], aL[im], bH[in]);
                    mma_bf16(acc[im][in], aH[im], bL[in]);
                }
        }
    }

    const int er = lane >> 2, ec = (lane & 3) * 2;
    if (mode == 0) {
        #pragma unroll
        for (int im = 0; im < 2; im++)
            #pragma unroll
            for (int in = 0; in < 8; in++) {
                const int n = n0 + wn + in * 8 + ec;
                const float bx = bias[n], by = bias[n + 1];
                const int mA = m0 + wm + im * 16 + er;
                float2 v0 = {acc[im][in][0] + bx, acc[im][in][1] + by};
                *reinterpret_cast<float2*>(Cf + (size_t)mA * HIDD + n) = v0;
                float2 v1 = {acc[im][in][2] + bx, acc[im][in][3] + by};
                *reinterpret_cast<float2*>(Cf + (size_t)(mA + 8) * HIDD + n) = v1;
            }
    } else {
        uint32_t* chiu = reinterpret_cast<uint32_t*>(ChiB + (size_t)z * MH);
        uint32_t* clou = reinterpret_cast<uint32_t*>(CloB + (size_t)z * MH);
        #pragma unroll
        for (int im = 0; im < 2; im++)
            #pragma unroll
            for (int in = 0; in < 8; in++) {
                const int n = n0 + wn + in * 8 + ec;
                const float bx = bias[n], by = bias[n + 1];
                const int mA = m0 + wm + im * 16 + er;
                float f0 = (acc[im][in][0] + bx) * scale;
                float f1 = (acc[im][in][1] + by) * scale;
                float f2 = (acc[im][in][2] + bx) * scale;
                float f3 = (acc[im][in][3] + by) * scale;
                __nv_bfloat16 h0 = __float2bfloat16(f0), h1 = __float2bfloat16(f1);
                __nv_bfloat16 h2 = __float2bfloat16(f2), h3 = __float2bfloat16(f3);
                size_t i0 = ((size_t)mA * HIDD + n) >> 1;
                size_t i1 = ((size_t)(mA + 8) * HIDD + n) >> 1;
                chiu[i0] = (uint32_t)__bfloat16_as_ushort(h0) |
                           ((uint32_t)__bfloat16_as_ushort(h1) << 16);
                chiu[i1] = (uint32_t)__bfloat16_as_ushort(h2) |
                           ((uint32_t)__bfloat16_as_ushort(h3) << 16);
                clou[i0] = pack2bf(f0 - __bfloat162float(h0), f1 - __bfloat162float(h1));
                clou[i1] = pack2bf(f2 - __bfloat162float(h2), f3 - __bfloat162float(h3));
            }
    }
}

// ---------------------------------------------------------------------------
// HMMA flash attention: presplit operands, 4-stage KV ring (ONE barrier/tile),
// exp2-domain softmax (Q pre-scaled by 0.125*log2e in the projection).
// ---------------------------------------------------------------------------
#define APAD 72
#define SQ_H 0
#define SQ_L (128 * APAD)
#define SKV  (2 * 128 * APAD)
#define KVS_K_L (64 * APAD)
#define KVS_V_H (2 * 64 * APAD)
#define KVS_V_L (3 * 64 * APAD)
#define KV_STG (4 * 64 * APAD)             // elems per stage
#define ASMEM_E (SKV + 4 * KV_STG)
#define ASMEM_B (ASMEM_E * 2)              // 184320 bytes
#define TKV (SS / 64)                      // 32

__global__ __launch_bounds__(256, 1) void attn_mma_kernel(
    const __nv_bfloat16* __restrict__ phi, const __nv_bfloat16* __restrict__ plo,
    __nv_bfloat16* __restrict__ chi, __nv_bfloat16* __restrict__ clo)
{
    extern __shared__ __nv_bfloat16 sm[];
    const uint32_t smb = smem_u32(sm);

    const int tid  = threadIdx.x;
    const int wid  = tid >> 5, lane = tid & 31;
    const int b    = blockIdx.y >> 4;
    const int h    = blockIdx.y & 15;
    const int q0   = blockIdx.x * 128;
    const int hoff = h * HDD;

    const __nv_bfloat16* qhi = phi;
    const __nv_bfloat16* qlo = plo;
    const __nv_bfloat16* khi = phi + MH;
    const __nv_bfloat16* klo = plo + MH;
    const __nv_bfloat16* vhi = phi + 2 * MH;
    const __nv_bfloat16* vlo = plo + 2 * MH;

    // ---- Q tile (own commit group)
    {
        const size_t qg = ((size_t)b * SS + q0) * HIDD + hoff;
        #pragma unroll
        for (int i = 0; i < 4; i++) {
            int idx = tid + i * 256;
            int r = idx >> 3, ch = idx & 7;
            cp16(smb + (uint32_t)(SQ_H + r * APAD + ch * 8) * 2,
                 qhi + qg + (size_t)r * HIDD + ch * 8);
            cp16(smb + (uint32_t)(SQ_L + r * APAD + ch * 8) * 2,
                 qlo + qg + (size_t)r * HIDD + ch * 8);
        }
        cp_commit();
    }

    auto issue_kv = [&](int kt) {
        const uint32_t sb = smb + (uint32_t)(SKV + (kt & 3) * KV_STG) * 2;
        #pragma unroll
        for (int i = 0; i < 2; i++) {
            int idx = tid + i * 256;
            int r = idx >> 3, ch = idx & 7;
            size_t g = ((size_t)b * SS + kt * 64 + r) * HIDD + hoff + ch * 8;
            uint32_t so = sb + (uint32_t)(r * APAD + ch * 8) * 2;
            cp16(so,                           khi + g);
            cp16(so + (uint32_t)KVS_K_L * 2,   klo + g);
            cp16(so + (uint32_t)KVS_V_H * 2,   vhi + g);
            cp16(so + (uint32_t)KVS_V_L * 2,   vlo + g);
        }
        cp_commit();
    };
    issue_kv(0); issue_kv(1); issue_kv(2);

    const uint32_t aRowOff = (uint32_t)((wid * 16 + (lane & 15)) * APAD +
                                        ((lane >> 4) << 3)) * 2;
    const uint32_t bRowOff = (uint32_t)(((lane & 7) + ((lane & 16) ? 8 : 0)) * APAD +
                                        ((lane & 8) ? 8 : 0)) * 2;
    const uint32_t vRowOff = (uint32_t)((lane & 15) * APAD +
                                        ((lane >> 4) << 3)) * 2;

    float O[8][4];
    #pragma unroll
    for (int j = 0; j < 8; j++)
        #pragma unroll
        for (int t = 0; t < 4; t++) O[j][t] = 0.f;
    float m0 = -1e30f, m1 = -1e30f, l0 = 0.f, l1 = 0.f;
    uint32_t qh[4][4], ql[4][4];

    for (int kt = 0; kt < TKV; kt++) {
        if (kt <= TKV - 3)      cp_wait2();
        else if (kt == TKV - 2) cp_wait1();
        else                    cp_wait0();
        __syncthreads();
        if (kt + 3 < TKV) issue_kv(kt + 3);

        if (kt == 0) {
            #pragma unroll
            for (int kk = 0; kk < 4; kk++) {
                ldm4(qh[kk], smb + (uint32_t)SQ_H * 2 + aRowOff + kk * 32);
                ldm4(ql[kk], smb + (uint32_t)SQ_L * 2 + aRowOff + kk * 32);
            }
        }

        const uint32_t kvb = smb + (uint32_t)(SKV + (kt & 3) * KV_STG) * 2;

        // ---- S = Q K^T (3-term, log2-domain scores)
        float sf[8][4];
        #pragma unroll
        for (int j = 0; j < 8; j++)
            #pragma unroll
            for (int t = 0; t < 4; t++) sf[j][t] = 0.f;

        #pragma unroll
        for (int kk = 0; kk < 4; kk++) {
            #pragma unroll
            for (int nb = 0; nb < 4; nb++) {
                uint32_t rh[4], rl[4];
                ldm4(rh, kvb + bRowOff + (uint32_t)(nb * 16 * APAD) * 2 + kk * 32);
                ldm4(rl, kvb + (uint32_t)KVS_K_L * 2 + bRowOff +
                          (uint32_t)(nb * 16 * APAD) * 2 + kk * 32);
                uint32_t bh0[2] = {rh[0], rh[1]}, bh1[2] = {rh[2], rh[3]};
                uint32_t bl0[2] = {rl[0], rl[1]}, bl1[2] = {rl[2], rl[3]};
                mma_bf16(sf[nb*2],   qh[kk], bh0);
                mma_bf16(sf[nb*2],   ql[kk], bh0);
                mma_bf16(sf[nb*2],   qh[kk], bl0);
                mma_bf16(sf[nb*2+1], qh[kk], bh1);
                mma_bf16(sf[nb*2+1], ql[kk], bh1);
                mma_bf16(sf[nb*2+1], qh[kk], bl1);
            }
        }

        // ---- online softmax (exp2 domain)
        float mx0 = -1e30f, mx1 = -1e30f;
        #pragma unroll
        for (int j = 0; j < 8; j++) {
            mx0 = fmaxf(mx0, fmaxf(sf[j][0], sf[j][1]));
            mx1 = fmaxf(mx1, fmaxf(sf[j][2], sf[j][3]));
        }
        mx0 = fmaxf(mx0, __shfl_xor_sync(0xffffffffu, mx0, 1));
        mx0 = fmaxf(mx0, __shfl_xor_sync(0xffffffffu, mx0, 2));
        mx1 = fmaxf(mx1, __shfl_xor_sync(0xffffffffu, mx1, 1));
        mx1 = fmaxf(mx1, __shfl_xor_sync(0xffffffffu, mx1, 2));
        float mn0 = fmaxf(m0, mx0), mn1 = fmaxf(m1, mx1);
        float c0 = exp2f(m0 - mn0), c1 = exp2f(m1 - mn1);
        m0 = mn0; m1 = mn1;

        float rs0 = 0.f, rs1 = 0.f;
        #pragma unroll
        for (int j = 0; j < 8; j++) {
            sf[j][0] = exp2f(sf[j][0] - mn0);
            sf[j][1] = exp2f(sf[j][1] - mn0);
            sf[j][2] = exp2f(sf[j][2] - mn1);
            sf[j][3] = exp2f(sf[j][3] - mn1);
            rs0 += sf[j][0] + sf[j][1];
            rs1 += sf[j][2] + sf[j][3];
        }
        rs0 += __shfl_xor_sync(0xffffffffu, rs0, 1);
        rs0 += __shfl_xor_sync(0xffffffffu, rs0, 2);
        rs1 += __shfl_xor_sync(0xffffffffu, rs1, 1);
        rs1 += __shfl_xor_sync(0xffffffffu, rs1, 2);
        l0 = l0 * c0 + rs0;
        l1 = l1 * c1 + rs1;

        #pragma unroll
        for (int j = 0; j < 8; j++) {
            O[j][0] *= c0; O[j][1] *= c0;
            O[j][2] *= c1; O[j][3] *= c1;
        }

        // ---- pack P hi/lo into A fragments
        uint32_t ph01[8], ph23[8], pl01[8], pl23[8];
        #pragma unroll
        for (int j = 0; j < 8; j++) {
            float p0 = sf[j][0], p1 = sf[j][1], p2 = sf[j][2], p3 = sf[j][3];
            __nv_bfloat16 h0 = __float2bfloat16(p0), h1 = __float2bfloat16(p1);
            __nv_bfloat16 h2 = __float2bfloat16(p2), h3 = __float2bfloat16(p3);
            ph01[j] = (uint32_t)__bfloat16_as_ushort(h0) |
                      ((uint32_t)__bfloat16_as_ushort(h1) << 16);
            ph23[j] = (uint32_t)__bfloat16_as_ushort(h2) |
                      ((uint32_t)__bfloat16_as_ushort(h3) << 16);
            pl01[j] = pack2bf(p0 - __bfloat162float(h0), p1 - __bfloat162float(h1));
            pl23[j] = pack2bf(p2 - __bfloat162float(h2), p3 - __bfloat162float(h3));
        }

        // ---- O += P V (3-term), V via ldmatrix.trans
        #pragma unroll
        for (int kk = 0; kk < 4; kk++) {
            uint32_t ah[4] = {ph01[2*kk], ph23[2*kk], ph01[2*kk+1], ph23[2*kk+1]};
            uint32_t al[4] = {pl01[2*kk], pl23[2*kk], pl01[2*kk+1], pl23[2*kk+1]};
            #pragma unroll
            for (int nb = 0; nb < 4; nb++) {
                uint32_t rh[4], rl[4];
                uint32_t voff = vRowOff + (uint32_t)(kk * 16 * APAD + nb * 16) * 2;
                ldm4t(rh, kvb + (uint32_t)KVS_V_H * 2 + voff);
                ldm4t(rl, kvb + (uint32_t)KVS_V_L * 2 + voff);
                uint32_t bh0[2] = {rh[0], rh[1]}, bh1[2] = {rh[2], rh[3]};
                uint32_t bl0[2] = {rl[0], rl[1]}, bl1[2] = {rl[2], rl[3]};
                mma_bf16(O[nb*2],   ah, bh0);
                mma_bf16(O[nb*2],   al, bh0);
                mma_bf16(O[nb*2],   ah, bl0);
                mma_bf16(O[nb*2+1], ah, bh1);
                mma_bf16(O[nb*2+1], al, bh1);
                mma_bf16(O[nb*2+1], ah, bl1);
            }
        }
        __syncthreads();
    }

    // ---- epilogue: ctx hi/lo
    const int er = lane >> 2, ec = (lane & 3) * 2;
    const float inv0 = 1.f / l0, inv1 = 1.f / l1;
    const int row0 = q0 + wid * 16 + er;
    uint32_t* chiu = reinterpret_cast<uint32_t*>(chi);
    uint32_t* clou = reinterpret_cast<uint32_t*>(clo);
    #pragma unroll
    for (int j = 0; j < 8; j++) {
        const int col = hoff + j * 8 + ec;
        float f0 = O[j][0] * inv0, f1 = O[j][1] * inv0;
        float f2 = O[j][2] * inv1, f3 = O[j][3] * inv1;
        __nv_bfloat16 h0 = __float2bfloat16(f0), h1 = __float2bfloat16(f1);
        __nv_bfloat16 h2 = __float2bfloat16(f2), h3 = __float2bfloat16(f3);
        size_t i0 = (((size_t)b * SS + row0) * HIDD + col) >> 1;
        size_t i1 = (((size_t)b * SS + row0 + 8) * HIDD + col) >> 1;
        chiu[i0] = (uint32_t)__bfloat16_as_ushort(h0) |
                   ((uint32_t)__bfloat16_as_ushort(h1) << 16);
        chiu[i1] = (uint32_t)__bfloat16_as_ushort(h2) |
                   ((uint32_t)__bfloat16_as_ushort(h3) << 16);
        clou[i0] = pack2bf(f0 - __bfloat162float(h0), f1 - __bfloat162float(h1));
        clou[i1] = pack2bf(f2 - __bfloat162float(h2), f3 - __bfloat162float(h3));
    }
}

// ---------------------------------------------------------------------------

extern "C" void kernel_launch(void* const* d_in, const int* in_sizes, int n_in,
                              void* d_out, int out_size)
{
    const float* query = (const float*)d_in[0];
    const float* key_  = (const float*)d_in[1];
    const float* value = (const float*)d_in[2];
    const float* Wq    = (const float*)d_in[3];
    const float* bq    = (const float*)d_in[4];
    const float* Wk    = (const float*)d_in[5];
    const float* bk    = (const float*)d_in[6];
    const float* Wv    = (const float*)d_in[7];
    const float* bv    = (const float*)d_in[8];
    const float* Wo    = (const float*)d_in[9];
    const float* bo    = (const float*)d_in[10];
    float* out = (float*)d_out;

    __nv_bfloat16 *inhi, *inlo, *wthi, *wtlo, *phi, *plo, *chi, *clo;
    cudaGetSymbolAddress((void**)&inhi, g_inhi);
    cudaGetSymbolAddress((void**)&inlo, g_inlo);
    cudaGetSymbolAddress((void**)&wthi, g_wthi);
    cudaGetSymbolAddress((void**)&wtlo, g_wtlo);
    cudaGetSymbolAddress((void**)&phi, g_phi);
    cudaGetSymbolAddress((void**)&plo, g_plo);
    cudaGetSymbolAddress((void**)&chi, g_chi);
    cudaGetSymbolAddress((void**)&clo, g_clo);

    cudaFuncSetAttribute(mma_gemm_kernel,
                         cudaFuncAttributeMaxDynamicSharedMemorySize, GSMEM);
    cudaFuncSetAttribute(attn_mma_kernel,
                         cudaFuncAttributeMaxDynamicSharedMemorySize, ASMEM_B);

    const int n4 = (int)(MH / 4);
    const float qscale = 0.125f * 1.44269504088896f;  // 1/sqrt(HD) * log2(e)

    // prep: all splits batched
    split3_kernel<<<dim3(n4 / 256, 3), 256>>>(query, key_, value, inhi, inlo, n4);
    splitT4_kernel<<<dim3(32, 32, 4), 256>>>(Wq, Wk, Wv, Wo, wthi, wtlo);

    // Q,K,V projections in ONE launch (grid.z = 3)
    mma_gemm_kernel<<<dim3(HIDD / 128, MM / 128, 3), 256, GSMEM>>>(
        inhi, inlo, wthi, wtlo, bq, bk, bv,
        nullptr, phi, plo, 1, qscale);

    // attention
    attn_mma_kernel<<<dim3(SS / 128, BB * NHH), 256, ASMEM_B>>>(phi, plo, chi, clo);

    // output projection (weight slot 3, fp32 out)
    mma_gemm_kernel<<<dim3(HIDD / 128, MM / 128, 1), 256, GSMEM>>>(
        chi, clo, wthi + 3 * HH, wtlo + 3 * HH, bo, bo, bo,
        out, nullptr, nullptr, 0, 1.0f);
}

// round 9
// speedup vs baseline: 3.0337x; 1.1197x over previous
#include <cuda_runtime.h>
#include <cuda_bf16.h>
#include <stdint.h>
#include <math.h>

#define BB   2
#define SS   2048
#define HIDD 1024
#define NHH  16
#define HDD  64
#define MM   (BB * SS)   // 4096 rows

static constexpr size_t MH = (size_t)MM * HIDD;
static constexpr size_t HH = (size_t)HIDD * HIDD;

// ---------------------------------------------------------------------------
// Scratch (bf16 hi/lo everywhere)
// ---------------------------------------------------------------------------
__device__ __nv_bfloat16 g_inhi[3 * MH];
__device__ __nv_bfloat16 g_inlo[3 * MH];
__device__ __nv_bfloat16 g_wthi[4 * HH];
__device__ __nv_bfloat16 g_wtlo[4 * HH];
__device__ __nv_bfloat16 g_phi[3 * MH];
__device__ __nv_bfloat16 g_plo[3 * MH];
__device__ __nv_bfloat16 g_chi[MH];
__device__ __nv_bfloat16 g_clo[MH];

// ---------------------------------------------------------------------------
// PTX helpers
// ---------------------------------------------------------------------------
__device__ __forceinline__ uint32_t smem_u32(const void* p) {
    uint32_t a;
    asm("{ .reg .u64 t; cvta.to.shared.u64 t, %1; cvt.u32.u64 %0, t; }"
        : "=r"(a) : "l"(p));
    return a;
}
__device__ __forceinline__ void cp16(uint32_t saddr, const void* g) {
    asm volatile("cp.async.cg.shared.global [%0], [%1], 16;"
                 :: "r"(saddr), "l"(g) : "memory");
}
__device__ __forceinline__ void cp_commit() {
    asm volatile("cp.async.commit_group;" ::: "memory");
}
__device__ __forceinline__ void cp_wait0() {
    asm volatile("cp.async.wait_group 0;" ::: "memory");
}
__device__ __forceinline__ void ldm4(uint32_t* r, uint32_t addr) {
    asm volatile("ldmatrix.sync.aligned.m8n8.x4.shared.b16 {%0,%1,%2,%3}, [%4];"
                 : "=r"(r[0]), "=r"(r[1]), "=r"(r[2]), "=r"(r[3]) : "r"(addr));
}
__device__ __forceinline__ void ldm4t(uint32_t* r, uint32_t addr) {
    asm volatile("ldmatrix.sync.aligned.m8n8.x4.trans.shared.b16 {%0,%1,%2,%3}, [%4];"
                 : "=r"(r[0]), "=r"(r[1]), "=r"(r[2]), "=r"(r[3]) : "r"(addr));
}
__device__ __forceinline__ void mma_bf16(float* c, const uint32_t* a,
                                         const uint32_t* b) {
    asm volatile(
        "mma.sync.aligned.m16n8k16.row.col.f32.bf16.bf16.f32 "
        "{%0,%1,%2,%3}, {%4,%5,%6,%7}, {%8,%9}, {%0,%1,%2,%3};"
        : "+f"(c[0]), "+f"(c[1]), "+f"(c[2]), "+f"(c[3])
        : "r"(a[0]), "r"(a[1]), "r"(a[2]), "r"(a[3]), "r"(b[0]), "r"(b[1]));
}
__device__ __forceinline__ uint32_t pack2bf(float a, float b) {
    return (uint32_t)__bfloat16_as_ushort(__float2bfloat16(a)) |
           ((uint32_t)__bfloat16_as_ushort(__float2bfloat16(b)) << 16);
}

// ---------------------------------------------------------------------------
// Batched fp32 -> bf16 hi/lo split (3 inputs via grid.y)
// ---------------------------------------------------------------------------
__global__ __launch_bounds__(256) void split3_kernel(
    const float* __restrict__ x0, const float* __restrict__ x1,
    const float* __restrict__ x2, __nv_bfloat16* __restrict__ hiB,
    __nv_bfloat16* __restrict__ loB, int n4)
{
    int i = blockIdx.x * 256 + threadIdx.x;
    if (i >= n4) return;
    const int z = blockIdx.y;
    const float* x = (z == 0) ? x0 : (z == 1) ? x1 : x2;
    float4 v = reinterpret_cast<const float4*>(x)[i];
    float f[4] = {v.x, v.y, v.z, v.w};
    unsigned short hs[4], ls[4];
    #pragma unroll
    for (int j = 0; j < 4; j++) {
        __nv_bfloat16 h = __float2bfloat16(f[j]);
        __nv_bfloat16 l = __float2bfloat16(f[j] - __bfloat162float(h));
        hs[j] = __bfloat16_as_ushort(h);
        ls[j] = __bfloat16_as_ushort(l);
    }
    uint2 ho, llo;
    ho.x  = (uint32_t)hs[0] | ((uint32_t)hs[1] << 16);
    ho.y  = (uint32_t)hs[2] | ((uint32_t)hs[3] << 16);
    llo.x = (uint32_t)ls[0] | ((uint32_t)ls[1] << 16);
    llo.y = (uint32_t)ls[2] | ((uint32_t)ls[3] << 16);
    size_t base = (size_t)z * (MH / 4);
    reinterpret_cast<uint2*>(hiB)[base + i] = ho;
    reinterpret_cast<uint2*>(loB)[base + i] = llo;
}

// ---------------------------------------------------------------------------
// Batched W [K][N] fp32 -> W^T [N][K] bf16 hi/lo (4 weights via grid.z)
// ---------------------------------------------------------------------------
__global__ __launch_bounds__(256) void splitT4_kernel(
    const float* __restrict__ W0, const float* __restrict__ W1,
    const float* __restrict__ W2, const float* __restrict__ W3,
    __nv_bfloat16* __restrict__ ThB, __nv_bfloat16* __restrict__ TlB)
{
    __shared__ float t[32][33];
    const int z = blockIdx.z;
    const float* W = (z == 0) ? W0 : (z == 1) ? W1 : (z == 2) ? W2 : W3;
    __nv_bfloat16* Th = ThB + (size_t)z * HH;
    __nv_bfloat16* Tl = TlB + (size_t)z * HH;
    int n0 = blockIdx.x * 32, k0 = blockIdx.y * 32;
    int tx = threadIdx.x & 31, ty = threadIdx.x >> 5;
    #pragma unroll
    for (int i = 0; i < 4; i++)
        t[ty + i * 8][tx] = W[(size_t)(k0 + ty + i * 8) * HIDD + n0 + tx];
    __syncthreads();
    #pragma unroll
    for (int i = 0; i < 4; i++) {
        float x = t[tx][ty + i * 8];
        __nv_bfloat16 h = __float2bfloat16(x);
        __nv_bfloat16 l = __float2bfloat16(x - __bfloat162float(h));
        size_t o = (size_t)(n0 + ty + i * 8) * HIDD + k0 + tx;
        Th[o] = h;
        Tl[o] = l;
    }
}

// ---------------------------------------------------------------------------
// HMMA 3x-emulated GEMM, 2-stage ring, 2 CTAs/SM.
// B fragments loaded per-ib and consumed immediately (low live regs).
// ---------------------------------------------------------------------------
#define TPAD 40
#define TILE_E (128 * TPAD)
#define TILE_B (TILE_E * 2)        // 10240
#define STAGE_B (4 * TILE_B)       // 40960
#define GSMEM (2 * STAGE_B)        // 81920
#define NCHUNK (HIDD / 32)         // 32

__global__ __launch_bounds__(256, 2) void mma_gemm_kernel(
    const __nv_bfloat16* __restrict__ AhiB, const __nv_bfloat16* __restrict__ AloB,
    const __nv_bfloat16* __restrict__ BthB, const __nv_bfloat16* __restrict__ BtlB,
    const float* __restrict__ b0, const float* __restrict__ b1,
    const float* __restrict__ b2,
    float* __restrict__ Cf, __nv_bfloat16* __restrict__ ChiB,
    __nv_bfloat16* __restrict__ CloB, int mode, float scaleQ)
{
    extern __shared__ __nv_bfloat16 sm[];
    const uint32_t smb = smem_u32(sm);

    const int tid  = threadIdx.x;
    const int wid  = tid >> 5, lane = tid & 31;
    const int z    = blockIdx.z;
    const int m0   = blockIdx.y * 128, n0 = blockIdx.x * 128;
    const int wm   = (wid >> 1) * 32;
    const int wn   = (wid & 1) * 64;

    const __nv_bfloat16* Ahi = AhiB + (size_t)z * MH;
    const __nv_bfloat16* Alo = AloB + (size_t)z * MH;
    const __nv_bfloat16* Bth = BthB + (size_t)z * HH;
    const __nv_bfloat16* Btl = BtlB + (size_t)z * HH;
    const float* bias = (z == 0) ? b0 : (z == 1) ? b1 : b2;
    const float scale = (z == 0) ? scaleQ : 1.0f;

    const int lrow = tid >> 1;
    const int lcol = (tid & 1) * 16;
    const size_t gA = (size_t)(m0 + lrow) * HIDD + lcol;
    const size_t gB = (size_t)(n0 + lrow) * HIDD + lcol;
    const uint32_t sO = smb + (uint32_t)(lrow * TPAD + lcol) * 2;

    float acc[2][8][4];
    #pragma unroll
    for (int im = 0; im < 2; im++)
        #pragma unroll
        for (int in = 0; in < 8; in++)
            #pragma unroll
            for (int j = 0; j < 4; j++) acc[im][in][j] = 0.f;

    const int a_row = wm + (lane & 15);
    const int a_col = (lane >> 4) << 3;
    const int b_row = wn + (lane & 7) + ((lane & 16) ? 8 : 0);
    const int b_col = (lane & 8) ? 8 : 0;
    const uint32_t aOff = (uint32_t)(a_row * TPAD + a_col) * 2;
    const uint32_t bOff = (uint32_t)(b_row * TPAD + b_col) * 2;

    auto issue = [&](int kc) {
        uint32_t so = sO + (uint32_t)(kc & 1) * STAGE_B;
        size_t ga = gA + (size_t)kc * 32, gb = gB + (size_t)kc * 32;
        cp16(so,              Ahi + ga); cp16(so + 16,              Ahi + ga + 8);
        cp16(so + TILE_B,     Alo + ga); cp16(so + TILE_B + 16,     Alo + ga + 8);
        cp16(so + 2*TILE_B,   Bth + gb); cp16(so + 2*TILE_B + 16,   Bth + gb + 8);
        cp16(so + 3*TILE_B,   Btl + gb); cp16(so + 3*TILE_B + 16,   Btl + gb + 8);
        cp_commit();
    };
    issue(0);

    for (int kc = 0; kc < NCHUNK; kc++) {
        cp_wait0();
        __syncthreads();
        if (kc + 1 < NCHUNK) issue(kc + 1);

        const uint32_t st = smb + (uint32_t)(kc & 1) * STAGE_B;
        #pragma unroll
        for (int ks = 0; ks < 32; ks += 16) {
            uint32_t aH[2][4], aL[2][4];
            #pragma unroll
            for (int im = 0; im < 2; im++) {
                ldm4(aH[im], st + aOff + (uint32_t)(im * 16 * TPAD + ks) * 2);
                ldm4(aL[im], st + TILE_B + aOff + (uint32_t)(im * 16 * TPAD + ks) * 2);
            }
            #pragma unroll
            for (int ib = 0; ib < 4; ib++) {
                uint32_t rh[4], rl[4];
                ldm4(rh, st + 2*TILE_B + bOff + (uint32_t)(ib * 16 * TPAD + ks) * 2);
                ldm4(rl, st + 3*TILE_B + bOff + (uint32_t)(ib * 16 * TPAD + ks) * 2);
                uint32_t bh0[2] = {rh[0], rh[1]}, bh1[2] = {rh[2], rh[3]};
                uint32_t bl0[2] = {rl[0], rl[1]}, bl1[2] = {rl[2], rl[3]};
                #pragma unroll
                for (int im = 0; im < 2; im++) {
                    mma_bf16(acc[im][ib*2],   aH[im], bh0);
                    mma_bf16(acc[im][ib*2],   aL[im], bh0);
                    mma_bf16(acc[im][ib*2],   aH[im], bl0);
                    mma_bf16(acc[im][ib*2+1], aH[im], bh1);
                    mma_bf16(acc[im][ib*2+1], aL[im], bh1);
                    mma_bf16(acc[im][ib*2+1], aH[im], bl1);
                }
            }
        }
    }

    const int er = lane >> 2, ec = (lane & 3) * 2;
    if (mode == 0) {
        #pragma unroll
        for (int im = 0; im < 2; im++)
            #pragma unroll
            for (int in = 0; in < 8; in++) {
                const int n = n0 + wn + in * 8 + ec;
                const float bx = bias[n], by = bias[n + 1];
                const int mA = m0 + wm + im * 16 + er;
                float2 v0 = {acc[im][in][0] + bx, acc[im][in][1] + by};
                *reinterpret_cast<float2*>(Cf + (size_t)mA * HIDD + n) = v0;
                float2 v1 = {acc[im][in][2] + bx, acc[im][in][3] + by};
                *reinterpret_cast<float2*>(Cf + (size_t)(mA + 8) * HIDD + n) = v1;
            }
    } else {
        uint32_t* chiu = reinterpret_cast<uint32_t*>(ChiB + (size_t)z * MH);
        uint32_t* clou = reinterpret_cast<uint32_t*>(CloB + (size_t)z * MH);
        #pragma unroll
        for (int im = 0; im < 2; im++)
            #pragma unroll
            for (int in = 0; in < 8; in++) {
                const int n = n0 + wn + in * 8 + ec;
                const float bx = bias[n], by = bias[n + 1];
                const int mA = m0 + wm + im * 16 + er;
                float f0 = (acc[im][in][0] + bx) * scale;
                float f1 = (acc[im][in][1] + by) * scale;
                float f2 = (acc[im][in][2] + bx) * scale;
                float f3 = (acc[im][in][3] + by) * scale;
                __nv_bfloat16 h0 = __float2bfloat16(f0), h1 = __float2bfloat16(f1);
                __nv_bfloat16 h2 = __float2bfloat16(f2), h3 = __float2bfloat16(f3);
                size_t i0 = ((size_t)mA * HIDD + n) >> 1;
                size_t i1 = ((size_t)(mA + 8) * HIDD + n) >> 1;
                chiu[i0] = (uint32_t)__bfloat16_as_ushort(h0) |
                           ((uint32_t)__bfloat16_as_ushort(h1) << 16);
                chiu[i1] = (uint32_t)__bfloat16_as_ushort(h2) |
                           ((uint32_t)__bfloat16_as_ushort(h3) << 16);
                clou[i0] = pack2bf(f0 - __bfloat162float(h0), f1 - __bfloat162float(h1));
                clou[i1] = pack2bf(f2 - __bfloat162float(h2), f3 - __bfloat162float(h3));
            }
    }
}

// ---------------------------------------------------------------------------
// HMMA flash attention: 2-stage KV ring, 2 CTAs/SM, Q fragments reloaded
// per tile (frees regs for P packs during the PV phase).
// ---------------------------------------------------------------------------
#define APAD 72
#define SQ_H 0
#define SQ_L (128 * APAD)
#define SKV  (2 * 128 * APAD)
#define KVS_K_L (64 * APAD)
#define KVS_V_H (2 * 64 * APAD)
#define KVS_V_L (3 * 64 * APAD)
#define KV_STG (4 * 64 * APAD)
#define ASMEM_E (SKV + 2 * KV_STG)
#define ASMEM_B (ASMEM_E * 2)              // 110592 bytes
#define TKV (SS / 64)                      // 32

__global__ __launch_bounds__(256, 2) void attn_mma_kernel(
    const __nv_bfloat16* __restrict__ phi, const __nv_bfloat16* __restrict__ plo,
    __nv_bfloat16* __restrict__ chi, __nv_bfloat16* __restrict__ clo)
{
    extern __shared__ __nv_bfloat16 sm[];
    const uint32_t smb = smem_u32(sm);

    const int tid  = threadIdx.x;
    const int wid  = tid >> 5, lane = tid & 31;
    const int b    = blockIdx.y >> 4;
    const int h    = blockIdx.y & 15;
    const int q0   = blockIdx.x * 128;
    const int hoff = h * HDD;

    const __nv_bfloat16* qhi = phi;
    const __nv_bfloat16* qlo = plo;
    const __nv_bfloat16* khi = phi + MH;
    const __nv_bfloat16* klo = plo + MH;
    const __nv_bfloat16* vhi = phi + 2 * MH;
    const __nv_bfloat16* vlo = plo + 2 * MH;

    // ---- Q tile (own commit group; first wait0 covers it)
    {
        const size_t qg = ((size_t)b * SS + q0) * HIDD + hoff;
        #pragma unroll
        for (int i = 0; i < 4; i++) {
            int idx = tid + i * 256;
            int r = idx >> 3, ch = idx & 7;
            cp16(smb + (uint32_t)(SQ_H + r * APAD + ch * 8) * 2,
                 qhi + qg + (size_t)r * HIDD + ch * 8);
            cp16(smb + (uint32_t)(SQ_L + r * APAD + ch * 8) * 2,
                 qlo + qg + (size_t)r * HIDD + ch * 8);
        }
        cp_commit();
    }

    auto issue_kv = [&](int kt) {
        const uint32_t sb = smb + (uint32_t)(SKV + (kt & 1) * KV_STG) * 2;
        #pragma unroll
        for (int i = 0; i < 2; i++) {
            int idx = tid + i * 256;
            int r = idx >> 3, ch = idx & 7;
            size_t g = ((size_t)b * SS + kt * 64 + r) * HIDD + hoff + ch * 8;
            uint32_t so = sb + (uint32_t)(r * APAD + ch * 8) * 2;
            cp16(so,                           khi + g);
            cp16(so + (uint32_t)KVS_K_L * 2,   klo + g);
            cp16(so + (uint32_t)KVS_V_H * 2,   vhi + g);
            cp16(so + (uint32_t)KVS_V_L * 2,   vlo + g);
        }
        cp_commit();
    };
    issue_kv(0);

    const uint32_t aRowOff = (uint32_t)((wid * 16 + (lane & 15)) * APAD +
                                        ((lane >> 4) << 3)) * 2;
    const uint32_t bRowOff = (uint32_t)(((lane & 7) + ((lane & 16) ? 8 : 0)) * APAD +
                                        ((lane & 8) ? 8 : 0)) * 2;
    const uint32_t vRowOff = (uint32_t)((lane & 15) * APAD +
                                        ((lane >> 4) << 3)) * 2;

    float O[8][4];
    #pragma unroll
    for (int j = 0; j < 8; j++)
        #pragma unroll
        for (int t = 0; t < 4; t++) O[j][t] = 0.f;
    float m0 = -1e30f, m1 = -1e30f, l0 = 0.f, l1 = 0.f;

    for (int kt = 0; kt < TKV; kt++) {
        cp_wait0();
        __syncthreads();
        if (kt + 1 < TKV) issue_kv(kt + 1);

        const uint32_t kvb = smb + (uint32_t)(SKV + (kt & 1) * KV_STG) * 2;

        // ---- S = Q K^T (3-term; Q frags reloaded per tile)
        float sf[8][4];
        #pragma unroll
        for (int j = 0; j < 8; j++)
            #pragma unroll
            for (int t = 0; t < 4; t++) sf[j][t] = 0.f;

        #pragma unroll
        for (int kk = 0; kk < 4; kk++) {
            uint32_t qh[4], ql[4];
            ldm4(qh, smb + (uint32_t)SQ_H * 2 + aRowOff + kk * 32);
            ldm4(ql, smb + (uint32_t)SQ_L * 2 + aRowOff + kk * 32);
            #pragma unroll
            for (int nb = 0; nb < 4; nb++) {
                uint32_t rh[4], rl[4];
                ldm4(rh, kvb + bRowOff + (uint32_t)(nb * 16 * APAD) * 2 + kk * 32);
                ldm4(rl, kvb + (uint32_t)KVS_K_L * 2 + bRowOff +
                          (uint32_t)(nb * 16 * APAD) * 2 + kk * 32);
                uint32_t bh0[2] = {rh[0], rh[1]}, bh1[2] = {rh[2], rh[3]};
                uint32_t bl0[2] = {rl[0], rl[1]}, bl1[2] = {rl[2], rl[3]};
                mma_bf16(sf[nb*2],   qh, bh0);
                mma_bf16(sf[nb*2],   ql, bh0);
                mma_bf16(sf[nb*2],   qh, bl0);
                mma_bf16(sf[nb*2+1], qh, bh1);
                mma_bf16(sf[nb*2+1], ql, bh1);
                mma_bf16(sf[nb*2+1], qh, bl1);
            }
        }

        // ---- online softmax (exp2 domain)
        float mx0 = -1e30f, mx1 = -1e30f;
        #pragma unroll
        for (int j = 0; j < 8; j++) {
            mx0 = fmaxf(mx0, fmaxf(sf[j][0], sf[j][1]));
            mx1 = fmaxf(mx1, fmaxf(sf[j][2], sf[j][3]));
        }
        mx0 = fmaxf(mx0, __shfl_xor_sync(0xffffffffu, mx0, 1));
        mx0 = fmaxf(mx0, __shfl_xor_sync(0xffffffffu, mx0, 2));
        mx1 = fmaxf(mx1, __shfl_xor_sync(0xffffffffu, mx1, 1));
        mx1 = fmaxf(mx1, __shfl_xor_sync(0xffffffffu, mx1, 2));
        float mn0 = fmaxf(m0, mx0), mn1 = fmaxf(m1, mx1);
        float c0 = exp2f(m0 - mn0), c1 = exp2f(m1 - mn1);
        m0 = mn0; m1 = mn1;

        float rs0 = 0.f, rs1 = 0.f;
        #pragma unroll
        for (int j = 0; j < 8; j++) {
            sf[j][0] = exp2f(sf[j][0] - mn0);
            sf[j][1] = exp2f(sf[j][1] - mn0);
            sf[j][2] = exp2f(sf[j][2] - mn1);
            sf[j][3] = exp2f(sf[j][3] - mn1);
            rs0 += sf[j][0] + sf[j][1];
            rs1 += sf[j][2] + sf[j][3];
        }
        rs0 += __shfl_xor_sync(0xffffffffu, rs0, 1);
        rs0 += __shfl_xor_sync(0xffffffffu, rs0, 2);
        rs1 += __shfl_xor_sync(0xffffffffu, rs1, 1);
        rs1 += __shfl_xor_sync(0xffffffffu, rs1, 2);
        l0 = l0 * c0 + rs0;
        l1 = l1 * c1 + rs1;

        #pragma unroll
        for (int j = 0; j < 8; j++) {
            O[j][0] *= c0; O[j][1] *= c0;
            O[j][2] *= c1; O[j][3] *= c1;
        }

        // ---- pack P hi/lo into A fragments (reuses Q's registers)
        uint32_t ph01[8], ph23[8], pl01[8], pl23[8];
        #pragma unroll
        for (int j = 0; j < 8; j++) {
            float p0 = sf[j][0], p1 = sf[j][1], p2 = sf[j][2], p3 = sf[j][3];
            __nv_bfloat16 h0 = __float2bfloat16(p0), h1 = __float2bfloat16(p1);
            __nv_bfloat16 h2 = __float2bfloat16(p2), h3 = __float2bfloat16(p3);
            ph01[j] = (uint32_t)__bfloat16_as_ushort(h0) |
                      ((uint32_t)__bfloat16_as_ushort(h1) << 16);
            ph23[j] = (uint32_t)__bfloat16_as_ushort(h2) |
                      ((uint32_t)__bfloat16_as_ushort(h3) << 16);
            pl01[j] = pack2bf(p0 - __bfloat162float(h0), p1 - __bfloat162float(h1));
            pl23[j] = pack2bf(p2 - __bfloat162float(h2), p3 - __bfloat162float(h3));
        }

        // ---- O += P V (3-term), V via ldmatrix.trans
        #pragma unroll
        for (int kk = 0; kk < 4; kk++) {
            uint32_t ah[4] = {ph01[2*kk], ph23[2*kk], ph01[2*kk+1], ph23[2*kk+1]};
            uint32_t al[4] = {pl01[2*kk], pl23[2*kk], pl01[2*kk+1], pl23[2*kk+1]};
            #pragma unroll
            for (int nb = 0; nb < 4; nb++) {
                uint32_t rh[4], rl[4];
                uint32_t voff = vRowOff + (uint32_t)(kk * 16 * APAD + nb * 16) * 2;
                ldm4t(rh, kvb + (uint32_t)KVS_V_H * 2 + voff);
                ldm4t(rl, kvb + (uint32_t)KVS_V_L * 2 + voff);
                uint32_t bh0[2] = {rh[0], rh[1]}, bh1[2] = {rh[2], rh[3]};
                uint32_t bl0[2] = {rl[0], rl[1]}, bl1[2] = {rl[2], rl[3]};
                mma_bf16(O[nb*2],   ah, bh0);
                mma_bf16(O[nb*2],   al, bh0);
                mma_bf16(O[nb*2],   ah, bl0);
                mma_bf16(O[nb*2+1], ah, bh1);
                mma_bf16(O[nb*2+1], al, bh1);
                mma_bf16(O[nb*2+1], ah, bl1);
            }
        }
        __syncthreads();
    }

    // ---- epilogue: ctx hi/lo
    const int er = lane >> 2, ec = (lane & 3) * 2;
    const float inv0 = 1.f / l0, inv1 = 1.f / l1;
    const int row0 = q0 + wid * 16 + er;
    uint32_t* chiu = reinterpret_cast<uint32_t*>(chi);
    uint32_t* clou = reinterpret_cast<uint32_t*>(clo);
    #pragma unroll
    for (int j = 0; j < 8; j++) {
        const int col = hoff + j * 8 + ec;
        float f0 = O[j][0] * inv0, f1 = O[j][1] * inv0;
        float f2 = O[j][2] * inv1, f3 = O[j][3] * inv1;
        __nv_bfloat16 h0 = __float2bfloat16(f0), h1 = __float2bfloat16(f1);
        __nv_bfloat16 h2 = __float2bfloat16(f2), h3 = __float2bfloat16(f3);
        size_t i0 = (((size_t)b * SS + row0) * HIDD + col) >> 1;
        size_t i1 = (((size_t)b * SS + row0 + 8) * HIDD + col) >> 1;
        chiu[i0] = (uint32_t)__bfloat16_as_ushort(h0) |
                   ((uint32_t)__bfloat16_as_ushort(h1) << 16);
        chiu[i1] = (uint32_t)__bfloat16_as_ushort(h2) |
                   ((uint32_t)__bfloat16_as_ushort(h3) << 16);
        clou[i0] = pack2bf(f0 - __bfloat162float(h0), f1 - __bfloat162float(h1));
        clou[i1] = pack2bf(f2 - __bfloat162float(h2), f3 - __bfloat162float(h3));
    }
}

// ---------------------------------------------------------------------------

extern "C" void kernel_launch(void* const* d_in, const int* in_sizes, int n_in,
                              void* d_out, int out_size)
{
    const float* query = (const float*)d_in[0];
    const float* key_  = (const float*)d_in[1];
    const float* value = (const float*)d_in[2];
    const float* Wq    = (const float*)d_in[3];
    const float* bq    = (const float*)d_in[4];
    const float* Wk    = (const float*)d_in[5];
    const float* bk    = (const float*)d_in[6];
    const float* Wv    = (const float*)d_in[7];
    const float* bv    = (const float*)d_in[8];
    const float* Wo    = (const float*)d_in[9];
    const float* bo    = (const float*)d_in[10];
    float* out = (float*)d_out;

    __nv_bfloat16 *inhi, *inlo, *wthi, *wtlo, *phi, *plo, *chi, *clo;
    cudaGetSymbolAddress((void**)&inhi, g_inhi);
    cudaGetSymbolAddress((void**)&inlo, g_inlo);
    cudaGetSymbolAddress((void**)&wthi, g_wthi);
    cudaGetSymbolAddress((void**)&wtlo, g_wtlo);
    cudaGetSymbolAddress((void**)&phi, g_phi);
    cudaGetSymbolAddress((void**)&plo, g_plo);
    cudaGetSymbolAddress((void**)&chi, g_chi);
    cudaGetSymbolAddress((void**)&clo, g_clo);

    cudaFuncSetAttribute(mma_gemm_kernel,
                         cudaFuncAttributeMaxDynamicSharedMemorySize, GSMEM);
    cudaFuncSetAttribute(attn_mma_kernel,
                         cudaFuncAttributeMaxDynamicSharedMemorySize, ASMEM_B);

    const int n4 = (int)(MH / 4);
    const float qscale = 0.125f * 1.44269504088896f;  // 1/sqrt(HD) * log2(e)

    split3_kernel<<<dim3(n4 / 256, 3), 256>>>(query, key_, value, inhi, inlo, n4);
    splitT4_kernel<<<dim3(32, 32, 4), 256>>>(Wq, Wk, Wv, Wo, wthi, wtlo);

    mma_gemm_kernel<<<dim3(HIDD / 128, MM / 128, 3), 256, GSMEM>>>(
        inhi, inlo, wthi, wtlo, bq, bk, bv,
        nullptr, phi, plo, 1, qscale);

    attn_mma_kernel<<<dim3(SS / 128, BB * NHH), 256, ASMEM_B>>>(phi, plo, chi, clo);

    mma_gemm_kernel<<<dim3(HIDD / 128, MM / 128, 1), 256, GSMEM>>>(
        chi, clo, wthi + 3 * HH, wtlo + 3 * HH, bo, bo, bo,
        out, nullptr, nullptr, 0, 1.0f);
}